// round 6
// baseline (speedup 1.0000x reference)
#include <cuda_runtime.h>
#include <math.h>
#include <stdint.h>

#define BN_EPS 1e-5f
#define LOG2E 1.4426950408889634f

// ---------------- scratch (static device buffers; no allocations) ----------
__device__ float g_kv  [64u*384u*784u];  // kv conv output  [b][o=384][n=784]
__device__ float g_q   [64u*128u*196u];  // q  conv output  [b][o=128][n=196]
__device__ float g_bias[ 8u*196u*784u];  // bias*log2e  [h][q=196][m=784]
__device__ float g_att [64u*256u*196u];  // hardswish(attn out) [b][c=256][n=196]

__device__ __forceinline__ float hardswish(float x) {
    float t = fminf(fmaxf(x + 3.f, 0.f), 6.f);
    return x * t * (1.f / 6.f);
}

__device__ __forceinline__ uint32_t f2tf32(float x) {
    uint32_t r;
    asm("cvt.rna.tf32.f32 %0, %1;" : "=r"(r) : "f"(x));
    return r;
}

__device__ __forceinline__ void mma_tf32(float c[4], const uint32_t a[4],
                                         uint32_t b0, uint32_t b1) {
    asm volatile(
        "mma.sync.aligned.m16n8k8.row.col.f32.tf32.tf32.f32 "
        "{%0,%1,%2,%3}, {%4,%5,%6,%7}, {%8,%9}, {%0,%1,%2,%3};"
        : "+f"(c[0]), "+f"(c[1]), "+f"(c[2]), "+f"(c[3])
        : "r"(a[0]), "r"(a[1]), "r"(a[2]), "r"(a[3]), "r"(b0), "r"(b1));
}

// ---------------- bias gather: g_bias[h][q][m] = ab[h][idxs[q][m]] * log2e --
__global__ void bias_gather_kernel(const float* __restrict__ ab,
                                   const int*   __restrict__ idxs,
                                   int n_off)
{
    int q = blockIdx.x;
    int h = blockIdx.y;
    int m = threadIdx.x;
    int idx = idxs[q * 784 + m];
    g_bias[((size_t)h * 196 + q) * 784 + m] = ab[h * n_off + idx] * LOG2E;
}

// ---------------- TF32 tensor-core GEMM + BN + hardswish (double-buffered) --
template<bool STRIDED>
__global__ void __launch_bounds__(256, 2)
conv_bn_hsw_tc_kernel(const float* __restrict__ X, int x_batch_stride, int ldx,
                      const float* __restrict__ W, int C,
                      const float* __restrict__ gam, const float* __restrict__ bet,
                      const float* __restrict__ mu,  const float* __restrict__ var,
                      float* __restrict__ Y, int O, int Ncols)
{
    __shared__ uint32_t As[2][128][20];
    __shared__ uint32_t Bs[2][64][20];

    const int b  = blockIdx.z;
    const float* Xb = X + (size_t)b * x_batch_stride;
    float*       Yb = Y + (size_t)b * O * Ncols;
    const int o0 = blockIdx.x * 128;
    const int n0 = blockIdx.y * 64;
    const int t  = threadIdx.x;

    const int warp = t >> 5;
    const int lane = t & 31;
    const int g    = lane >> 2;
    const int t4   = lane & 3;
    const int wm   = warp >> 2;
    const int wn   = warp & 3;
    const int mrow0 = wm * 64;
    const int ncol0 = wn * 16;

    const int arow0 = t >> 2, aseg = t & 3;
    const int bn    = t & 63;
    const int bk0   = t >> 6;
    int bgn = n0 + bn;
    bool bok = (bgn < Ncols);
    if (STRIDED && bok) bgn = 2 * (bgn / 14) * 28 + 2 * (bgn % 14);

    float acc[4][2][4];
    #pragma unroll
    for (int i = 0; i < 4; i++)
        #pragma unroll
        for (int j = 0; j < 2; j++)
            #pragma unroll
            for (int e = 0; e < 4; e++) acc[i][j][e] = 0.f;

    float4 avr[2];
    float  bvr[4];

    #pragma unroll
    for (int r = 0; r < 2; r++)
        avr[r] = *reinterpret_cast<const float4*>(&W[(o0 + arow0 + r * 64) * C + aseg * 4]);
    #pragma unroll
    for (int r = 0; r < 4; r++)
        bvr[r] = bok ? Xb[(size_t)(bk0 + r * 4) * ldx + bgn] : 0.f;

    int buf = 0;
    #pragma unroll
    for (int r = 0; r < 2; r++) {
        int row = arow0 + r * 64;
        As[0][row][aseg * 4 + 0] = f2tf32(avr[r].x);
        As[0][row][aseg * 4 + 1] = f2tf32(avr[r].y);
        As[0][row][aseg * 4 + 2] = f2tf32(avr[r].z);
        As[0][row][aseg * 4 + 3] = f2tf32(avr[r].w);
    }
    #pragma unroll
    for (int r = 0; r < 4; r++)
        Bs[0][bn][bk0 + r * 4] = f2tf32(bvr[r]);
    __syncthreads();

    const int nslab = C >> 4;
    for (int s = 0; s < nslab; s++) {
        const bool more = (s + 1 < nslab);
        const int c1 = (s + 1) << 4;
        if (more) {
            #pragma unroll
            for (int r = 0; r < 2; r++)
                avr[r] = *reinterpret_cast<const float4*>(
                    &W[(o0 + arow0 + r * 64) * C + c1 + aseg * 4]);
            #pragma unroll
            for (int r = 0; r < 4; r++)
                bvr[r] = bok ? Xb[(size_t)(c1 + bk0 + r * 4) * ldx + bgn] : 0.f;
        }

        #pragma unroll
        for (int ks = 0; ks < 16; ks += 8) {
            uint32_t a[4][4];
            #pragma unroll
            for (int mf = 0; mf < 4; mf++) {
                int rb = mrow0 + mf * 16;
                a[mf][0] = As[buf][rb + g    ][ks + t4    ];
                a[mf][1] = As[buf][rb + g + 8][ks + t4    ];
                a[mf][2] = As[buf][rb + g    ][ks + t4 + 4];
                a[mf][3] = As[buf][rb + g + 8][ks + t4 + 4];
            }
            uint32_t bfr[2][2];
            #pragma unroll
            for (int nf = 0; nf < 2; nf++) {
                int cb = ncol0 + nf * 8;
                bfr[nf][0] = Bs[buf][cb + g][ks + t4    ];
                bfr[nf][1] = Bs[buf][cb + g][ks + t4 + 4];
            }
            #pragma unroll
            for (int mf = 0; mf < 4; mf++)
                #pragma unroll
                for (int nf = 0; nf < 2; nf++)
                    mma_tf32(acc[mf][nf], a[mf], bfr[nf][0], bfr[nf][1]);
        }

        if (more) {
            int nb = buf ^ 1;
            #pragma unroll
            for (int r = 0; r < 2; r++) {
                int row = arow0 + r * 64;
                As[nb][row][aseg * 4 + 0] = f2tf32(avr[r].x);
                As[nb][row][aseg * 4 + 1] = f2tf32(avr[r].y);
                As[nb][row][aseg * 4 + 2] = f2tf32(avr[r].z);
                As[nb][row][aseg * 4 + 3] = f2tf32(avr[r].w);
            }
            #pragma unroll
            for (int r = 0; r < 4; r++)
                Bs[nb][bn][bk0 + r * 4] = f2tf32(bvr[r]);
        }
        __syncthreads();
        buf ^= 1;
    }

    #pragma unroll
    for (int mf = 0; mf < 4; mf++) {
        #pragma unroll
        for (int half = 0; half < 2; half++) {
            int o = o0 + mrow0 + mf * 16 + g + half * 8;
            float sc = gam[o] * rsqrtf(var[o] + BN_EPS);
            float mm = mu[o], bt = bet[o];
            #pragma unroll
            for (int nf = 0; nf < 2; nf++) {
                #pragma unroll
                for (int e = 0; e < 2; e++) {
                    int n = n0 + ncol0 + nf * 8 + t4 * 2 + e;
                    if (n < Ncols) {
                        float y = (acc[mf][nf][half * 2 + e] - mm) * sc + bt;
                        Yb[(size_t)o * Ncols + n] = hardswish(y);
                    }
                }
            }
        }
    }
}

// ---------------- tensor-core flash attention (32 q per warp) ---------------
// grid (512 bh, 2 qblocks), 128 threads / 4 warps. Each warp owns two 16-row
// q-tiles (u=0,1); V fragments and K/V smem tiles are shared across both.
__global__ void __launch_bounds__(128)
attention_tc_kernel()
{
    const int bh = blockIdx.x;
    const int b = bh >> 3, h = bh & 7;
    const int qb = blockIdx.y;
    const int t = threadIdx.x;
    const int warp = t >> 5, lane = t & 31;
    const int g = lane >> 2, t4 = lane & 3;

    __shared__ uint32_t Ks[56 * 20];         // K^T: [m][d] pitch 20 (tf32)
    __shared__ uint32_t Vs[32 * 60];         // V:   [d][m] pitch 60 (tf32)
    __shared__ uint32_t Ps[4][2][16 * 60];   // per-warp per-tile P (tf32)

    const float* kvb  = g_kv   + ((size_t)b * 384 + (size_t)h * 48) * 784;
    const float* bsh  = g_bias + (size_t)h * 196 * 784;

    // division-free loader coordinates
    const int kd = t >> 3, km = t & 7;
    const int vd = t >> 2, vm = t & 3;
    const float* kK = kvb + (size_t)kd * 784 + km;
    const float* kV = kvb + (size_t)(16 + vd) * 784 + vm;
    uint32_t* KsT = Ks + km * 20 + kd;
    uint32_t* VsT = Vs + vd * 60 + vm;

    const int qbase = qb * 128 + warp * 32;
    int qA[2], qB[2];
    qA[0] = qbase + g;       qB[0] = qbase + g + 8;
    qA[1] = qbase + 16 + g;  qB[1] = qbase + 24 + g;

    // Q fragments for both tiles, pre-scaled by 0.25*log2e
    uint32_t qa[2][2][4];
    const float QS = 0.25f * LOG2E;
    #pragma unroll
    for (int u = 0; u < 2; u++) {
        #pragma unroll
        for (int ks = 0; ks < 2; ks++) {
            #pragma unroll
            for (int cc = 0; cc < 2; cc++) {
                int d = ks * 8 + t4 + cc * 4;
                float vA = (qA[u] < 196) ? g_q[((size_t)b * 128 + h * 16 + d) * 196 + qA[u]] * QS : 0.f;
                float vB = (qB[u] < 196) ? g_q[((size_t)b * 128 + h * 16 + d) * 196 + qB[u]] * QS : 0.f;
                qa[u][ks][cc * 2 + 0] = f2tf32(vA);
                qa[u][ks][cc * 2 + 1] = f2tf32(vB);
            }
        }
    }

    float oc[2][4][4];
    #pragma unroll
    for (int u = 0; u < 2; u++)
        #pragma unroll
        for (int v = 0; v < 4; v++)
            #pragma unroll
            for (int e = 0; e < 4; e++) oc[u][v][e] = 0.f;
    float rm0[2] = {-1e30f, -1e30f}, rm1[2] = {-1e30f, -1e30f};
    float rl0[2] = {0.f, 0.f},       rl1[2] = {0.f, 0.f};

    for (int m0 = 0; m0 < 784; m0 += 56) {
        // ---- cooperative loads: K transposed, V natural (division-free)
        #pragma unroll
        for (int j = 0; j < 7; j++)
            KsT[(8 * j) * 20] = f2tf32(kK[m0 + 8 * j]);
        #pragma unroll
        for (int j = 0; j < 14; j++)
            VsT[4 * j] = f2tf32(kV[m0 + 4 * j]);
        __syncthreads();

        // ---- per q-tile: S = bias + Q K^T, online softmax, P -> smem
        #pragma unroll
        for (int u = 0; u < 2; u++) {
            float sc[7][4];
            #pragma unroll
            for (int j = 0; j < 7; j++) {
                int m = m0 + j * 8 + 2 * t4;
                if (qA[u] < 196) {
                    float2 v = *reinterpret_cast<const float2*>(&bsh[(size_t)qA[u] * 784 + m]);
                    sc[j][0] = v.x; sc[j][1] = v.y;
                } else { sc[j][0] = 0.f; sc[j][1] = 0.f; }
                if (qB[u] < 196) {
                    float2 v = *reinterpret_cast<const float2*>(&bsh[(size_t)qB[u] * 784 + m]);
                    sc[j][2] = v.x; sc[j][3] = v.y;
                } else { sc[j][2] = 0.f; sc[j][3] = 0.f; }
            }
            #pragma unroll
            for (int ks = 0; ks < 2; ks++) {
                #pragma unroll
                for (int j = 0; j < 7; j++) {
                    uint32_t b0 = Ks[(j * 8 + g) * 20 + ks * 8 + t4];
                    uint32_t b1 = Ks[(j * 8 + g) * 20 + ks * 8 + t4 + 4];
                    mma_tf32(sc[j], qa[u][ks], b0, b1);
                }
            }

            float mx0 = rm0[u], mx1 = rm1[u];
            #pragma unroll
            for (int j = 0; j < 7; j++) {
                mx0 = fmaxf(mx0, fmaxf(sc[j][0], sc[j][1]));
                mx1 = fmaxf(mx1, fmaxf(sc[j][2], sc[j][3]));
            }
            mx0 = fmaxf(mx0, __shfl_xor_sync(0xffffffffu, mx0, 1));
            mx0 = fmaxf(mx0, __shfl_xor_sync(0xffffffffu, mx0, 2));
            mx1 = fmaxf(mx1, __shfl_xor_sync(0xffffffffu, mx1, 1));
            mx1 = fmaxf(mx1, __shfl_xor_sync(0xffffffffu, mx1, 2));

            float a0 = exp2f(rm0[u] - mx0), a1 = exp2f(rm1[u] - mx1);
            rl0[u] *= a0; rl1[u] *= a1; rm0[u] = mx0; rm1[u] = mx1;
            #pragma unroll
            for (int v = 0; v < 4; v++) {
                oc[u][v][0] *= a0; oc[u][v][1] *= a0;
                oc[u][v][2] *= a1; oc[u][v][3] *= a1;
            }

            float s0 = 0.f, s1 = 0.f;
            #pragma unroll
            for (int j = 0; j < 7; j++) {
                float p0 = exp2f(sc[j][0] - mx0);
                float p1 = exp2f(sc[j][1] - mx0);
                float p2 = exp2f(sc[j][2] - mx1);
                float p3 = exp2f(sc[j][3] - mx1);
                s0 += p0 + p1; s1 += p2 + p3;
                uint2 lo = make_uint2(f2tf32(p0), f2tf32(p1));
                uint2 hi = make_uint2(f2tf32(p2), f2tf32(p3));
                *reinterpret_cast<uint2*>(&Ps[warp][u][g * 60 + j * 8 + 2 * t4]) = lo;
                *reinterpret_cast<uint2*>(&Ps[warp][u][(g + 8) * 60 + j * 8 + 2 * t4]) = hi;
            }
            s0 += __shfl_xor_sync(0xffffffffu, s0, 1);
            s0 += __shfl_xor_sync(0xffffffffu, s0, 2);
            s1 += __shfl_xor_sync(0xffffffffu, s1, 1);
            s1 += __shfl_xor_sync(0xffffffffu, s1, 2);
            rl0[u] += s0; rl1[u] += s1;
        }

        __syncwarp();

        // ---- out += P @ V^T : V fragments loaded once, used for both tiles
        #pragma unroll
        for (int kk = 0; kk < 7; kk++) {
            uint32_t pa0[4], pa1[4];
            pa0[0] = Ps[warp][0][g * 60 + kk * 8 + t4];
            pa0[1] = Ps[warp][0][(g + 8) * 60 + kk * 8 + t4];
            pa0[2] = Ps[warp][0][g * 60 + kk * 8 + t4 + 4];
            pa0[3] = Ps[warp][0][(g + 8) * 60 + kk * 8 + t4 + 4];
            pa1[0] = Ps[warp][1][g * 60 + kk * 8 + t4];
            pa1[1] = Ps[warp][1][(g + 8) * 60 + kk * 8 + t4];
            pa1[2] = Ps[warp][1][g * 60 + kk * 8 + t4 + 4];
            pa1[3] = Ps[warp][1][(g + 8) * 60 + kk * 8 + t4 + 4];
            #pragma unroll
            for (int v = 0; v < 4; v++) {
                uint32_t b0 = Vs[(v * 8 + g) * 60 + kk * 8 + t4];
                uint32_t b1 = Vs[(v * 8 + g) * 60 + kk * 8 + t4 + 4];
                mma_tf32(oc[0][v], pa0, b0, b1);
                mma_tf32(oc[1][v], pa1, b0, b1);
            }
        }
        __syncthreads();
    }

    // ---- normalize, hardswish, store (both tiles)
    #pragma unroll
    for (int u = 0; u < 2; u++) {
        float inv0 = 1.f / rl0[u], inv1 = 1.f / rl1[u];
        #pragma unroll
        for (int v = 0; v < 4; v++) {
            #pragma unroll
            for (int e = 0; e < 2; e++) {
                int d = v * 8 + 2 * t4 + e;
                if (qA[u] < 196)
                    g_att[((size_t)b * 256 + h * 32 + d) * 196 + qA[u]] = hardswish(oc[u][v][e] * inv0);
                if (qB[u] < 196)
                    g_att[((size_t)b * 256 + h * 32 + d) * 196 + qB[u]] = hardswish(oc[u][v][2 + e] * inv1);
            }
        }
    }
}

// ---------------- launch -----------------------------------------------------
extern "C" void kernel_launch(void* const* d_in, const int* in_sizes, int n_in,
                              void* d_out, int out_size)
{
    const float* x      = (const float*)d_in[0];
    const float* kv_w   = (const float*)d_in[1];
    const float* kv_g   = (const float*)d_in[2];
    const float* kv_b   = (const float*)d_in[3];
    const float* kv_m   = (const float*)d_in[4];
    const float* kv_v   = (const float*)d_in[5];
    const float* q_w    = (const float*)d_in[6];
    const float* q_g    = (const float*)d_in[7];
    const float* q_b    = (const float*)d_in[8];
    const float* q_m    = (const float*)d_in[9];
    const float* q_v    = (const float*)d_in[10];
    const float* proj_w = (const float*)d_in[11];
    const float* proj_g = (const float*)d_in[12];
    const float* proj_b = (const float*)d_in[13];
    const float* proj_m = (const float*)d_in[14];
    const float* proj_v = (const float*)d_in[15];
    const float* ab     = (const float*)d_in[16];
    const int*   idxs   = (const int*)  d_in[17];
    const int n_off = in_sizes[16] / 8;

    float* out = (float*)d_out;

    float *p_kv, *p_q, *p_att;
    cudaGetSymbolAddress((void**)&p_kv,  g_kv);
    cudaGetSymbolAddress((void**)&p_q,   g_q);
    cudaGetSymbolAddress((void**)&p_att, g_att);

    bias_gather_kernel<<<dim3(196, 8), 784>>>(ab, idxs, n_off);

    conv_bn_hsw_tc_kernel<false><<<dim3(3, 13, 64), 256>>>(
        x, 256 * 784, 784, kv_w, 256, kv_g, kv_b, kv_m, kv_v, p_kv, 384, 784);

    conv_bn_hsw_tc_kernel<true><<<dim3(1, 4, 64), 256>>>(
        x, 256 * 784, 784, q_w, 256, q_g, q_b, q_m, q_v, p_q, 128, 196);

    attention_tc_kernel<<<dim3(512, 2), 128>>>();

    conv_bn_hsw_tc_kernel<false><<<dim3(4, 4, 64), 256>>>(
        p_att, 256 * 196, 196, proj_w, 256, proj_g, proj_b, proj_m, proj_v, out, 512, 196);
}

// round 7
// speedup vs baseline: 1.2955x; 1.2955x over previous
#include <cuda_runtime.h>
#include <math.h>
#include <stdint.h>

#define BN_EPS 1e-5f
#define LOG2E 1.4426950408889634f

// ---------------- scratch (static device buffers; no allocations) ----------
__device__ float g_kv  [64u*384u*784u];  // kv conv output  [b][o=384][n=784]
__device__ float g_q   [64u*128u*196u];  // q  conv output  [b][o=128][n=196]
__device__ float g_bias[ 8u*196u*784u];  // bias*log2e  [h][q=196][m=784]
__device__ float g_att [64u*256u*196u];  // hardswish(attn out) [b][c=256][n=196]

__device__ __forceinline__ float hardswish(float x) {
    float t = fminf(fmaxf(x + 3.f, 0.f), 6.f);
    return x * t * (1.f / 6.f);
}

__device__ __forceinline__ uint32_t f2tf32(float x) {
    uint32_t r;
    asm("cvt.rna.tf32.f32 %0, %1;" : "=r"(r) : "f"(x));
    return r;
}

__device__ __forceinline__ void mma_tf32(float c[4], const uint32_t a[4],
                                         uint32_t b0, uint32_t b1) {
    asm volatile(
        "mma.sync.aligned.m16n8k8.row.col.f32.tf32.tf32.f32 "
        "{%0,%1,%2,%3}, {%4,%5,%6,%7}, {%8,%9}, {%0,%1,%2,%3};"
        : "+f"(c[0]), "+f"(c[1]), "+f"(c[2]), "+f"(c[3])
        : "r"(a[0]), "r"(a[1]), "r"(a[2]), "r"(a[3]), "r"(b0), "r"(b1));
}

// ---------------- bias gather: g_bias[h][q][m] = ab[h][idxs[q][m]] * log2e --
__global__ void bias_gather_kernel(const float* __restrict__ ab,
                                   const int*   __restrict__ idxs,
                                   int n_off)
{
    int q = blockIdx.x;
    int h = blockIdx.y;
    int m = threadIdx.x;
    int idx = idxs[q * 784 + m];
    g_bias[((size_t)h * 196 + q) * 784 + m] = ab[h * n_off + idx] * LOG2E;
}

// ---------------- TF32 GEMM + BN + hardswish, batch-flattened N -------------
// Y[b][o][n] = hardswish( (sum_c W[o][c]*X[b][c][col(n)] - mu[o])*sc[o]+bt[o] )
// Global columns = b*NperB + n, guaranteed multiple of 128.
// Block tile 128(O) x 128(cols), 8 warps (2x4), warp tile 64x32, K-slab 16,
// double-buffered (LDG s+1 | MMA s | STS s+1 | sync).
template<bool STRIDED>
__global__ void __launch_bounds__(256, 2)
conv_bn_hsw_tc_kernel(const float* __restrict__ X, int xbs, int ldx,
                      const float* __restrict__ W, int C,
                      const float* __restrict__ gam, const float* __restrict__ bet,
                      const float* __restrict__ mu,  const float* __restrict__ var,
                      float* __restrict__ Y, int O, int NperB)
{
    __shared__ uint32_t As[2][128][20];   // A[row][k] tf32, pitch 20
    __shared__ uint32_t Bs[2][128][20];   // B[col][k] tf32, pitch 20

    const int o0 = blockIdx.x * 128;
    const int n0 = blockIdx.y * 128;
    const int t  = threadIdx.x;

    const int warp = t >> 5;
    const int lane = t & 31;
    const int g    = lane >> 2;
    const int t4   = lane & 3;
    const int wm   = warp >> 2;      // 0..1
    const int wn   = warp & 3;       // 0..3
    const int mrow0 = wm * 64;
    const int ncol0 = wn * 32;

    // A loader: rows arow0, arow0+64; cols aseg*4..+3
    const int arow0 = t >> 2, aseg = t & 3;
    // B loader: column bcol (0..127), k-half bks (8 rows)
    const int bcol = t & 127;
    const int bks  = t >> 7;
    {
    }
    const int colg = n0 + bcol;
    const int bb   = colg / NperB;
    int nn = colg - bb * NperB;
    if (STRIDED) nn = 2 * (nn / 14) * 28 + 2 * (nn % 14);
    const float* bsrc = X + (size_t)bb * xbs + nn;

    float acc[4][4][4];
    #pragma unroll
    for (int i = 0; i < 4; i++)
        #pragma unroll
        for (int j = 0; j < 4; j++)
            #pragma unroll
            for (int e = 0; e < 4; e++) acc[i][j][e] = 0.f;

    float4 avr[2];
    float  bvr[8];

    // ---- prologue: LDG slab 0
    #pragma unroll
    for (int r = 0; r < 2; r++)
        avr[r] = *reinterpret_cast<const float4*>(&W[(o0 + arow0 + r * 64) * C + aseg * 4]);
    #pragma unroll
    for (int j = 0; j < 8; j++)
        bvr[j] = bsrc[(size_t)(bks * 8 + j) * ldx];

    // STS slab 0
    #pragma unroll
    for (int r = 0; r < 2; r++) {
        int row = arow0 + r * 64;
        uint4 w = make_uint4(f2tf32(avr[r].x), f2tf32(avr[r].y),
                             f2tf32(avr[r].z), f2tf32(avr[r].w));
        *reinterpret_cast<uint4*>(&As[0][row][aseg * 4]) = w;
    }
    {
        uint4 w0 = make_uint4(f2tf32(bvr[0]), f2tf32(bvr[1]), f2tf32(bvr[2]), f2tf32(bvr[3]));
        uint4 w1 = make_uint4(f2tf32(bvr[4]), f2tf32(bvr[5]), f2tf32(bvr[6]), f2tf32(bvr[7]));
        *reinterpret_cast<uint4*>(&Bs[0][bcol][bks * 8 + 0]) = w0;
        *reinterpret_cast<uint4*>(&Bs[0][bcol][bks * 8 + 4]) = w1;
    }
    __syncthreads();

    int buf = 0;
    const int nslab = C >> 4;
    for (int s = 0; s < nslab; s++) {
        const bool more = (s + 1 < nslab);
        const int c1 = (s + 1) << 4;
        if (more) {
            #pragma unroll
            for (int r = 0; r < 2; r++)
                avr[r] = *reinterpret_cast<const float4*>(
                    &W[(o0 + arow0 + r * 64) * C + c1 + aseg * 4]);
            #pragma unroll
            for (int j = 0; j < 8; j++)
                bvr[j] = bsrc[(size_t)(c1 + bks * 8 + j) * ldx];
        }

        // ---- compute slab s
        #pragma unroll
        for (int ks = 0; ks < 16; ks += 8) {
            uint32_t a[4][4];
            #pragma unroll
            for (int mf = 0; mf < 4; mf++) {
                int rb = mrow0 + mf * 16;
                a[mf][0] = As[buf][rb + g    ][ks + t4    ];
                a[mf][1] = As[buf][rb + g + 8][ks + t4    ];
                a[mf][2] = As[buf][rb + g    ][ks + t4 + 4];
                a[mf][3] = As[buf][rb + g + 8][ks + t4 + 4];
            }
            uint32_t bfr[4][2];
            #pragma unroll
            for (int nf = 0; nf < 4; nf++) {
                int cb = ncol0 + nf * 8;
                bfr[nf][0] = Bs[buf][cb + g][ks + t4    ];
                bfr[nf][1] = Bs[buf][cb + g][ks + t4 + 4];
            }
            #pragma unroll
            for (int mf = 0; mf < 4; mf++)
                #pragma unroll
                for (int nf = 0; nf < 4; nf++)
                    mma_tf32(acc[mf][nf], a[mf], bfr[nf][0], bfr[nf][1]);
        }

        if (more) {
            int nb = buf ^ 1;
            #pragma unroll
            for (int r = 0; r < 2; r++) {
                int row = arow0 + r * 64;
                uint4 w = make_uint4(f2tf32(avr[r].x), f2tf32(avr[r].y),
                                     f2tf32(avr[r].z), f2tf32(avr[r].w));
                *reinterpret_cast<uint4*>(&As[nb][row][aseg * 4]) = w;
            }
            uint4 w0 = make_uint4(f2tf32(bvr[0]), f2tf32(bvr[1]), f2tf32(bvr[2]), f2tf32(bvr[3]));
            uint4 w1 = make_uint4(f2tf32(bvr[4]), f2tf32(bvr[5]), f2tf32(bvr[6]), f2tf32(bvr[7]));
            *reinterpret_cast<uint4*>(&Bs[nb][bcol][bks * 8 + 0]) = w0;
            *reinterpret_cast<uint4*>(&Bs[nb][bcol][bks * 8 + 4]) = w1;
        }
        __syncthreads();
        buf ^= 1;
    }

    // ---- epilogue: BN + hardswish. Precompute (b, n) for the 8 columns.
    int ecb[8]; int ecn[8];
    #pragma unroll
    for (int nf = 0; nf < 4; nf++) {
        #pragma unroll
        for (int e = 0; e < 2; e++) {
            int idx = nf * 2 + e;
            int col = n0 + ncol0 + nf * 8 + t4 * 2 + e;
            int cb2 = col / NperB;
            ecb[idx] = cb2;
            ecn[idx] = col - cb2 * NperB;
        }
    }
    #pragma unroll
    for (int mf = 0; mf < 4; mf++) {
        #pragma unroll
        for (int half = 0; half < 2; half++) {
            int o = o0 + mrow0 + mf * 16 + g + half * 8;
            float sc = gam[o] * rsqrtf(var[o] + BN_EPS);
            float mm = mu[o], bt = bet[o];
            #pragma unroll
            for (int nf = 0; nf < 4; nf++) {
                #pragma unroll
                for (int e = 0; e < 2; e++) {
                    int idx = nf * 2 + e;
                    float y = (acc[mf][nf][half * 2 + e] - mm) * sc + bt;
                    Y[((size_t)ecb[idx] * O + o) * NperB + ecn[idx]] = hardswish(y);
                }
            }
        }
    }
}

// ---------------- tensor-core flash attention (R5 version) ------------------
// grid (512 bh, 4 qblocks), 128 threads (4 warps, each owns 16 queries).
__global__ void __launch_bounds__(128)
attention_tc_kernel()
{
    const int bh = blockIdx.x;
    const int b = bh >> 3, h = bh & 7;
    const int qb = blockIdx.y;
    const int t = threadIdx.x;
    const int warp = t >> 5, lane = t & 31;
    const int g = lane >> 2, t4 = lane & 3;

    __shared__ uint32_t Ks[56 * 20];      // K^T: [m][d] pitch 20 (tf32)
    __shared__ uint32_t Vs[32 * 60];      // V:   [d][m] pitch 60 (tf32)
    __shared__ uint32_t Ps[4][16 * 60];   // per-warp P: [q][m] pitch 60 (tf32)

    const float* kvb  = g_kv   + ((size_t)b * 384 + (size_t)h * 48) * 784;
    const float* bsh  = g_bias + (size_t)h * 196 * 784;

    // division-free loader coordinates
    const int kd = t >> 3, km = t & 7;
    const int vd = t >> 2, vm = t & 3;
    const float* kK = kvb + (size_t)kd * 784 + km;
    const float* kV = kvb + (size_t)(16 + vd) * 784 + vm;
    uint32_t* KsT = Ks + km * 20 + kd;
    uint32_t* VsT = Vs + vd * 60 + vm;

    const int q0 = qb * 64 + warp * 16;
    const int qA = q0 + g, qB = q0 + g + 8;

    uint32_t qa[2][4];
    const float QS = 0.25f * LOG2E;
    #pragma unroll
    for (int ks = 0; ks < 2; ks++) {
        #pragma unroll
        for (int cc = 0; cc < 2; cc++) {
            int d = ks * 8 + t4 + cc * 4;
            float vA = (qA < 196) ? g_q[((size_t)b * 128 + h * 16 + d) * 196 + qA] * QS : 0.f;
            float vB = (qB < 196) ? g_q[((size_t)b * 128 + h * 16 + d) * 196 + qB] * QS : 0.f;
            qa[ks][cc * 2 + 0] = f2tf32(vA);
            qa[ks][cc * 2 + 1] = f2tf32(vB);
        }
    }

    float oc[4][4];
    #pragma unroll
    for (int v = 0; v < 4; v++)
        #pragma unroll
        for (int e = 0; e < 4; e++) oc[v][e] = 0.f;
    float rm0 = -1e30f, rm1 = -1e30f, rl0 = 0.f, rl1 = 0.f;

    for (int m0 = 0; m0 < 784; m0 += 56) {
        #pragma unroll
        for (int j = 0; j < 7; j++)
            KsT[(8 * j) * 20] = f2tf32(kK[m0 + 8 * j]);
        #pragma unroll
        for (int j = 0; j < 14; j++)
            VsT[4 * j] = f2tf32(kV[m0 + 4 * j]);
        __syncthreads();

        float sc[7][4];
        #pragma unroll
        for (int j = 0; j < 7; j++) {
            int m = m0 + j * 8 + 2 * t4;
            if (qA < 196) {
                float2 v = *reinterpret_cast<const float2*>(&bsh[(size_t)qA * 784 + m]);
                sc[j][0] = v.x; sc[j][1] = v.y;
            } else { sc[j][0] = 0.f; sc[j][1] = 0.f; }
            if (qB < 196) {
                float2 v = *reinterpret_cast<const float2*>(&bsh[(size_t)qB * 784 + m]);
                sc[j][2] = v.x; sc[j][3] = v.y;
            } else { sc[j][2] = 0.f; sc[j][3] = 0.f; }
        }
        #pragma unroll
        for (int ks = 0; ks < 2; ks++) {
            #pragma unroll
            for (int j = 0; j < 7; j++) {
                uint32_t b0 = Ks[(j * 8 + g) * 20 + ks * 8 + t4];
                uint32_t b1 = Ks[(j * 8 + g) * 20 + ks * 8 + t4 + 4];
                mma_tf32(sc[j], qa[ks], b0, b1);
            }
        }

        float mx0 = rm0, mx1 = rm1;
        #pragma unroll
        for (int j = 0; j < 7; j++) {
            mx0 = fmaxf(mx0, fmaxf(sc[j][0], sc[j][1]));
            mx1 = fmaxf(mx1, fmaxf(sc[j][2], sc[j][3]));
        }
        mx0 = fmaxf(mx0, __shfl_xor_sync(0xffffffffu, mx0, 1));
        mx0 = fmaxf(mx0, __shfl_xor_sync(0xffffffffu, mx0, 2));
        mx1 = fmaxf(mx1, __shfl_xor_sync(0xffffffffu, mx1, 1));
        mx1 = fmaxf(mx1, __shfl_xor_sync(0xffffffffu, mx1, 2));

        float a0 = exp2f(rm0 - mx0), a1 = exp2f(rm1 - mx1);
        rl0 *= a0; rl1 *= a1; rm0 = mx0; rm1 = mx1;
        #pragma unroll
        for (int v = 0; v < 4; v++) {
            oc[v][0] *= a0; oc[v][1] *= a0;
            oc[v][2] *= a1; oc[v][3] *= a1;
        }

        float s0 = 0.f, s1 = 0.f;
        #pragma unroll
        for (int j = 0; j < 7; j++) {
            float p0 = exp2f(sc[j][0] - mx0);
            float p1 = exp2f(sc[j][1] - mx0);
            float p2 = exp2f(sc[j][2] - mx1);
            float p3 = exp2f(sc[j][3] - mx1);
            s0 += p0 + p1; s1 += p2 + p3;
            uint2 lo = make_uint2(f2tf32(p0), f2tf32(p1));
            uint2 hi = make_uint2(f2tf32(p2), f2tf32(p3));
            *reinterpret_cast<uint2*>(&Ps[warp][g * 60 + j * 8 + 2 * t4]) = lo;
            *reinterpret_cast<uint2*>(&Ps[warp][(g + 8) * 60 + j * 8 + 2 * t4]) = hi;
        }
        s0 += __shfl_xor_sync(0xffffffffu, s0, 1);
        s0 += __shfl_xor_sync(0xffffffffu, s0, 2);
        s1 += __shfl_xor_sync(0xffffffffu, s1, 1);
        s1 += __shfl_xor_sync(0xffffffffu, s1, 2);
        rl0 += s0; rl1 += s1;

        __syncwarp();

        #pragma unroll
        for (int kk = 0; kk < 7; kk++) {
            uint32_t pa[4];
            pa[0] = Ps[warp][g * 60 + kk * 8 + t4];
            pa[1] = Ps[warp][(g + 8) * 60 + kk * 8 + t4];
            pa[2] = Ps[warp][g * 60 + kk * 8 + t4 + 4];
            pa[3] = Ps[warp][(g + 8) * 60 + kk * 8 + t4 + 4];
            #pragma unroll
            for (int v = 0; v < 4; v++) {
                uint32_t b0 = Vs[(v * 8 + g) * 60 + kk * 8 + t4];
                uint32_t b1 = Vs[(v * 8 + g) * 60 + kk * 8 + t4 + 4];
                mma_tf32(oc[v], pa, b0, b1);
            }
        }
        __syncthreads();
    }

    float inv0 = 1.f / rl0, inv1 = 1.f / rl1;
    #pragma unroll
    for (int v = 0; v < 4; v++) {
        #pragma unroll
        for (int e = 0; e < 2; e++) {
            int d = v * 8 + 2 * t4 + e;
            if (qA < 196)
                g_att[((size_t)b * 256 + h * 32 + d) * 196 + qA] = hardswish(oc[v][e] * inv0);
            if (qB < 196)
                g_att[((size_t)b * 256 + h * 32 + d) * 196 + qB] = hardswish(oc[v][2 + e] * inv1);
        }
    }
}

// ---------------- launch -----------------------------------------------------
extern "C" void kernel_launch(void* const* d_in, const int* in_sizes, int n_in,
                              void* d_out, int out_size)
{
    const float* x      = (const float*)d_in[0];
    const float* kv_w   = (const float*)d_in[1];
    const float* kv_g   = (const float*)d_in[2];
    const float* kv_b   = (const float*)d_in[3];
    const float* kv_m   = (const float*)d_in[4];
    const float* kv_v   = (const float*)d_in[5];
    const float* q_w    = (const float*)d_in[6];
    const float* q_g    = (const float*)d_in[7];
    const float* q_b    = (const float*)d_in[8];
    const float* q_m    = (const float*)d_in[9];
    const float* q_v    = (const float*)d_in[10];
    const float* proj_w = (const float*)d_in[11];
    const float* proj_g = (const float*)d_in[12];
    const float* proj_b = (const float*)d_in[13];
    const float* proj_m = (const float*)d_in[14];
    const float* proj_v = (const float*)d_in[15];
    const float* ab     = (const float*)d_in[16];
    const int*   idxs   = (const int*)  d_in[17];
    const int n_off = in_sizes[16] / 8;

    float* out = (float*)d_out;

    float *p_kv, *p_q, *p_att;
    cudaGetSymbolAddress((void**)&p_kv,  g_kv);
    cudaGetSymbolAddress((void**)&p_q,   g_q);
    cudaGetSymbolAddress((void**)&p_att, g_att);

    // 1) bias table [h][q][m], *log2e
    bias_gather_kernel<<<dim3(196, 8), 784>>>(ab, idxs, n_off);

    // 2) kv: cols = 64*784 = 50176 = 392*128
    conv_bn_hsw_tc_kernel<false><<<dim3(3, 392), 256>>>(
        x, 256 * 784, 784, kv_w, 256, kv_g, kv_b, kv_m, kv_v, p_kv, 384, 784);

    // 3) q: cols = 64*196 = 12544 = 98*128 (strided input gather)
    conv_bn_hsw_tc_kernel<true><<<dim3(1, 98), 256>>>(
        x, 256 * 784, 784, q_w, 256, q_g, q_b, q_m, q_v, p_q, 128, 196);

    // 4) tensor-core flash attention -> g_att (with pre-proj hardswish)
    attention_tc_kernel<<<dim3(512, 4), 128>>>();

    // 5) proj: cols = 64*196 = 12544 = 98*128
    conv_bn_hsw_tc_kernel<false><<<dim3(4, 98), 256>>>(
        p_att, 256 * 196, 196, proj_w, 256, proj_g, proj_b, proj_m, proj_v, out, 512, 196);
}

// round 8
// speedup vs baseline: 1.3328x; 1.0288x over previous
#include <cuda_runtime.h>
#include <math.h>
#include <stdint.h>

#define BN_EPS 1e-5f
#define LOG2E 1.4426950408889634f

// ---------------- scratch (static device buffers; no allocations) ----------
__device__ float g_kv  [64u*384u*784u];  // kv conv output  [b][o=384][n=784]
__device__ float g_q   [64u*128u*196u];  // q  conv output  [b][o=128][n=196]
__device__ float g_bias[ 8u*196u*784u];  // bias*log2e  [h][q=196][m=784]
__device__ float g_att [64u*256u*196u];  // hardswish(attn out) [b][c=256][n=196]

__device__ __forceinline__ float hardswish(float x) {
    float t = fminf(fmaxf(x + 3.f, 0.f), 6.f);
    return x * t * (1.f / 6.f);
}

__device__ __forceinline__ uint32_t f2tf32(float x) {
    uint32_t r;
    asm("cvt.rna.tf32.f32 %0, %1;" : "=r"(r) : "f"(x));
    return r;
}

__device__ __forceinline__ float exp2fast(float x) {
    float y;
    asm("ex2.approx.f32 %0, %1;" : "=f"(y) : "f"(x));
    return y;
}

__device__ __forceinline__ void mma_tf32(float c[4], const uint32_t a[4],
                                         uint32_t b0, uint32_t b1) {
    asm volatile(
        "mma.sync.aligned.m16n8k8.row.col.f32.tf32.tf32.f32 "
        "{%0,%1,%2,%3}, {%4,%5,%6,%7}, {%8,%9}, {%0,%1,%2,%3};"
        : "+f"(c[0]), "+f"(c[1]), "+f"(c[2]), "+f"(c[3])
        : "r"(a[0]), "r"(a[1]), "r"(a[2]), "r"(a[3]), "r"(b0), "r"(b1));
}

// ---------------- bias gather: g_bias[h][q][m] = ab[h][idxs[q][m]] * log2e --
__global__ void bias_gather_kernel(const float* __restrict__ ab,
                                   const int*   __restrict__ idxs,
                                   int n_off)
{
    int q = blockIdx.x;
    int h = blockIdx.y;
    int m = threadIdx.x;
    int idx = idxs[q * 784 + m];
    g_bias[((size_t)h * 196 + q) * 784 + m] = ab[h * n_off + idx] * LOG2E;
}

// ---------------- TF32 GEMM + BN + hardswish, batch-flattened N -------------
template<bool STRIDED>
__global__ void __launch_bounds__(256, 2)
conv_bn_hsw_tc_kernel(const float* __restrict__ X, int xbs, int ldx,
                      const float* __restrict__ W, int C,
                      const float* __restrict__ gam, const float* __restrict__ bet,
                      const float* __restrict__ mu,  const float* __restrict__ var,
                      float* __restrict__ Y, int O, int NperB)
{
    __shared__ uint32_t As[2][128][20];
    __shared__ uint32_t Bs[2][128][20];

    const int o0 = blockIdx.x * 128;
    const int n0 = blockIdx.y * 128;
    const int t  = threadIdx.x;

    const int warp = t >> 5;
    const int lane = t & 31;
    const int g    = lane >> 2;
    const int t4   = lane & 3;
    const int wm   = warp >> 2;
    const int wn   = warp & 3;
    const int mrow0 = wm * 64;
    const int ncol0 = wn * 32;

    const int arow0 = t >> 2, aseg = t & 3;
    const int bcol = t & 127;
    const int bks  = t >> 7;
    const int colg = n0 + bcol;
    const int bb   = colg / NperB;
    int nn = colg - bb * NperB;
    if (STRIDED) nn = 2 * (nn / 14) * 28 + 2 * (nn % 14);
    const float* bsrc = X + (size_t)bb * xbs + nn;

    float acc[4][4][4];
    #pragma unroll
    for (int i = 0; i < 4; i++)
        #pragma unroll
        for (int j = 0; j < 4; j++)
            #pragma unroll
            for (int e = 0; e < 4; e++) acc[i][j][e] = 0.f;

    float4 avr[2];
    float  bvr[8];

    #pragma unroll
    for (int r = 0; r < 2; r++)
        avr[r] = *reinterpret_cast<const float4*>(&W[(o0 + arow0 + r * 64) * C + aseg * 4]);
    #pragma unroll
    for (int j = 0; j < 8; j++)
        bvr[j] = bsrc[(size_t)(bks * 8 + j) * ldx];

    #pragma unroll
    for (int r = 0; r < 2; r++) {
        int row = arow0 + r * 64;
        uint4 w = make_uint4(f2tf32(avr[r].x), f2tf32(avr[r].y),
                             f2tf32(avr[r].z), f2tf32(avr[r].w));
        *reinterpret_cast<uint4*>(&As[0][row][aseg * 4]) = w;
    }
    {
        uint4 w0 = make_uint4(f2tf32(bvr[0]), f2tf32(bvr[1]), f2tf32(bvr[2]), f2tf32(bvr[3]));
        uint4 w1 = make_uint4(f2tf32(bvr[4]), f2tf32(bvr[5]), f2tf32(bvr[6]), f2tf32(bvr[7]));
        *reinterpret_cast<uint4*>(&Bs[0][bcol][bks * 8 + 0]) = w0;
        *reinterpret_cast<uint4*>(&Bs[0][bcol][bks * 8 + 4]) = w1;
    }
    __syncthreads();

    int buf = 0;
    const int nslab = C >> 4;
    for (int s = 0; s < nslab; s++) {
        const bool more = (s + 1 < nslab);
        const int c1 = (s + 1) << 4;
        if (more) {
            #pragma unroll
            for (int r = 0; r < 2; r++)
                avr[r] = *reinterpret_cast<const float4*>(
                    &W[(o0 + arow0 + r * 64) * C + c1 + aseg * 4]);
            #pragma unroll
            for (int j = 0; j < 8; j++)
                bvr[j] = bsrc[(size_t)(c1 + bks * 8 + j) * ldx];
        }

        #pragma unroll
        for (int ks = 0; ks < 16; ks += 8) {
            uint32_t a[4][4];
            #pragma unroll
            for (int mf = 0; mf < 4; mf++) {
                int rb = mrow0 + mf * 16;
                a[mf][0] = As[buf][rb + g    ][ks + t4    ];
                a[mf][1] = As[buf][rb + g + 8][ks + t4    ];
                a[mf][2] = As[buf][rb + g    ][ks + t4 + 4];
                a[mf][3] = As[buf][rb + g + 8][ks + t4 + 4];
            }
            uint32_t bfr[4][2];
            #pragma unroll
            for (int nf = 0; nf < 4; nf++) {
                int cb = ncol0 + nf * 8;
                bfr[nf][0] = Bs[buf][cb + g][ks + t4    ];
                bfr[nf][1] = Bs[buf][cb + g][ks + t4 + 4];
            }
            #pragma unroll
            for (int mf = 0; mf < 4; mf++)
                #pragma unroll
                for (int nf = 0; nf < 4; nf++)
                    mma_tf32(acc[mf][nf], a[mf], bfr[nf][0], bfr[nf][1]);
        }

        if (more) {
            int nb = buf ^ 1;
            #pragma unroll
            for (int r = 0; r < 2; r++) {
                int row = arow0 + r * 64;
                uint4 w = make_uint4(f2tf32(avr[r].x), f2tf32(avr[r].y),
                                     f2tf32(avr[r].z), f2tf32(avr[r].w));
                *reinterpret_cast<uint4*>(&As[nb][row][aseg * 4]) = w;
            }
            uint4 w0 = make_uint4(f2tf32(bvr[0]), f2tf32(bvr[1]), f2tf32(bvr[2]), f2tf32(bvr[3]));
            uint4 w1 = make_uint4(f2tf32(bvr[4]), f2tf32(bvr[5]), f2tf32(bvr[6]), f2tf32(bvr[7]));
            *reinterpret_cast<uint4*>(&Bs[nb][bcol][bks * 8 + 0]) = w0;
            *reinterpret_cast<uint4*>(&Bs[nb][bcol][bks * 8 + 4]) = w1;
        }
        __syncthreads();
        buf ^= 1;
    }

    int ecb[8]; int ecn[8];
    #pragma unroll
    for (int nf = 0; nf < 4; nf++) {
        #pragma unroll
        for (int e = 0; e < 2; e++) {
            int idx = nf * 2 + e;
            int col = n0 + ncol0 + nf * 8 + t4 * 2 + e;
            int cb2 = col / NperB;
            ecb[idx] = cb2;
            ecn[idx] = col - cb2 * NperB;
        }
    }
    #pragma unroll
    for (int mf = 0; mf < 4; mf++) {
        #pragma unroll
        for (int half = 0; half < 2; half++) {
            int o = o0 + mrow0 + mf * 16 + g + half * 8;
            float sc = gam[o] * rsqrtf(var[o] + BN_EPS);
            float mm = mu[o], bt = bet[o];
            #pragma unroll
            for (int nf = 0; nf < 4; nf++) {
                #pragma unroll
                for (int e = 0; e < 2; e++) {
                    int idx = nf * 2 + e;
                    float y = (acc[mf][nf][half * 2 + e] - mm) * sc + bt;
                    Y[((size_t)ecb[idx] * O + o) * NperB + ecn[idx]] = hardswish(y);
                }
            }
        }
    }
}

// ---------------- tensor-core flash attention (k-permuted smem, LDS.64) -----
// grid (512 bh, 4 qblocks), 128 threads / 4 warps, 16 queries per warp.
// Smem layouts permute the mma k-dimension within groups of 8
// (phys = (k&3)*2 + (k>>2)) so each B/A fragment pair is one LDS.64.
__global__ void __launch_bounds__(128)
attention_tc_kernel()
{
    const int bh = blockIdx.x;
    const int b = bh >> 3, h = bh & 7;
    const int qb = blockIdx.y;
    const int t = threadIdx.x;
    const int warp = t >> 5, lane = t & 31;
    const int g = lane >> 2, t4 = lane & 3;

    __shared__ uint32_t Ks[56 * 24];      // K^T: [m][d-perm] pitch 24
    __shared__ uint32_t Vs[32 * 56];      // V:   [d][m-perm] pitch 56
    __shared__ uint32_t Ps[4][16 * 56];   // per-warp P: [q][m-perm] pitch 56

    const float* kvb  = g_kv   + ((size_t)b * 384 + (size_t)h * 48) * 784;
    const float* bsh  = g_bias + (size_t)h * 196 * 784;

    // staging coordinates (division-free)
    const int kd = t >> 3, km = t & 7;    // K: d 0..15, m = km + 8j
    const int vd = t >> 2, vm = t & 3;    // V: d 0..31, m = vm + 4j
    const float* kK = kvb + (size_t)kd * 784 + km;
    const float* kV = kvb + (size_t)(16 + vd) * 784 + vm;
    const int kd_phys = ((kd >> 3) << 3) + ((kd & 3) << 1) + ((kd & 7) >> 2);
    uint32_t* KsT = Ks + km * 24 + kd_phys;
    uint32_t* VsT = Vs + vd * 56 + vm * 2;

    const int q0 = qb * 64 + warp * 16;
    const int qA = q0 + g, qB = q0 + g + 8;

    uint32_t qa[2][4];
    const float QS = 0.25f * LOG2E;
    #pragma unroll
    for (int ks = 0; ks < 2; ks++) {
        #pragma unroll
        for (int cc = 0; cc < 2; cc++) {
            int d = ks * 8 + t4 + cc * 4;
            float vA = (qA < 196) ? g_q[((size_t)b * 128 + h * 16 + d) * 196 + qA] * QS : 0.f;
            float vB = (qB < 196) ? g_q[((size_t)b * 128 + h * 16 + d) * 196 + qB] * QS : 0.f;
            qa[ks][cc * 2 + 0] = f2tf32(vA);
            qa[ks][cc * 2 + 1] = f2tf32(vB);
        }
    }

    float oc[4][4];
    #pragma unroll
    for (int v = 0; v < 4; v++)
        #pragma unroll
        for (int e = 0; e < 4; e++) oc[v][e] = 0.f;
    float rm0 = -1e30f, rm1 = -1e30f, rl0 = 0.f, rl1 = 0.f;

    // P-store physical column base: cols 2t4, 2t4+1 -> phys pp, pp+2
    const int pp = ((t4 & 1) << 2) + (t4 >> 1);

    for (int m0 = 0; m0 < 784; m0 += 56) {
        // ---- staging: K [m][d-perm], V [d][m-perm]
        #pragma unroll
        for (int j = 0; j < 7; j++)
            KsT[(8 * j) * 24] = f2tf32(kK[m0 + 8 * j]);
        #pragma unroll
        for (int j = 0; j < 14; j++)
            VsT[(j >> 1) * 8 + (j & 1)] = f2tf32(kV[m0 + 4 * j]);
        __syncthreads();

        // ---- S = bias + Q K^T
        float sc[7][4];
        #pragma unroll
        for (int j = 0; j < 7; j++) {
            int m = m0 + j * 8 + 2 * t4;
            if (qA < 196) {
                float2 v = *reinterpret_cast<const float2*>(&bsh[(size_t)qA * 784 + m]);
                sc[j][0] = v.x; sc[j][1] = v.y;
            } else { sc[j][0] = 0.f; sc[j][1] = 0.f; }
            if (qB < 196) {
                float2 v = *reinterpret_cast<const float2*>(&bsh[(size_t)qB * 784 + m]);
                sc[j][2] = v.x; sc[j][3] = v.y;
            } else { sc[j][2] = 0.f; sc[j][3] = 0.f; }
        }
        #pragma unroll
        for (int ks = 0; ks < 2; ks++) {
            #pragma unroll
            for (int j = 0; j < 7; j++) {
                uint2 kk2 = *reinterpret_cast<const uint2*>(
                    &Ks[(j * 8 + g) * 24 + ks * 8 + t4 * 2]);
                mma_tf32(sc[j], qa[ks], kk2.x, kk2.y);
            }
        }

        // ---- online softmax (exp2 domain)
        float mx0 = rm0, mx1 = rm1;
        #pragma unroll
        for (int j = 0; j < 7; j++) {
            mx0 = fmaxf(mx0, fmaxf(sc[j][0], sc[j][1]));
            mx1 = fmaxf(mx1, fmaxf(sc[j][2], sc[j][3]));
        }
        mx0 = fmaxf(mx0, __shfl_xor_sync(0xffffffffu, mx0, 1));
        mx0 = fmaxf(mx0, __shfl_xor_sync(0xffffffffu, mx0, 2));
        mx1 = fmaxf(mx1, __shfl_xor_sync(0xffffffffu, mx1, 1));
        mx1 = fmaxf(mx1, __shfl_xor_sync(0xffffffffu, mx1, 2));

        float a0 = exp2fast(rm0 - mx0), a1 = exp2fast(rm1 - mx1);
        rl0 *= a0; rl1 *= a1; rm0 = mx0; rm1 = mx1;
        #pragma unroll
        for (int v = 0; v < 4; v++) {
            oc[v][0] *= a0; oc[v][1] *= a0;
            oc[v][2] *= a1; oc[v][3] *= a1;
        }

        float s0 = 0.f, s1 = 0.f;
        #pragma unroll
        for (int j = 0; j < 7; j++) {
            float p0 = exp2fast(sc[j][0] - mx0);
            float p1 = exp2fast(sc[j][1] - mx0);
            float p2 = exp2fast(sc[j][2] - mx1);
            float p3 = exp2fast(sc[j][3] - mx1);
            s0 += p0 + p1; s1 += p2 + p3;
            uint32_t* prow0 = &Ps[warp][g * 56 + j * 8 + pp];
            uint32_t* prow1 = &Ps[warp][(g + 8) * 56 + j * 8 + pp];
            prow0[0] = f2tf32(p0);
            prow0[2] = f2tf32(p1);
            prow1[0] = f2tf32(p2);
            prow1[2] = f2tf32(p3);
        }
        s0 += __shfl_xor_sync(0xffffffffu, s0, 1);
        s0 += __shfl_xor_sync(0xffffffffu, s0, 2);
        s1 += __shfl_xor_sync(0xffffffffu, s1, 1);
        s1 += __shfl_xor_sync(0xffffffffu, s1, 2);
        rl0 += s0; rl1 += s1;

        __syncwarp();

        // ---- out += P @ V^T (all fragment pairs via LDS.64)
        #pragma unroll
        for (int kk = 0; kk < 7; kk++) {
            uint2 pl = *reinterpret_cast<const uint2*>(
                &Ps[warp][g * 56 + kk * 8 + t4 * 2]);
            uint2 ph = *reinterpret_cast<const uint2*>(
                &Ps[warp][(g + 8) * 56 + kk * 8 + t4 * 2]);
            uint32_t pa[4];
            pa[0] = pl.x; pa[1] = ph.x; pa[2] = pl.y; pa[3] = ph.y;
            #pragma unroll
            for (int v = 0; v < 4; v++) {
                uint2 vv = *reinterpret_cast<const uint2*>(
                    &Vs[(v * 8 + g) * 56 + kk * 8 + t4 * 2]);
                mma_tf32(oc[v], pa, vv.x, vv.y);
            }
        }
        __syncthreads();
    }

    // ---- normalize, hardswish, store
    float inv0 = 1.f / rl0, inv1 = 1.f / rl1;
    #pragma unroll
    for (int v = 0; v < 4; v++) {
        #pragma unroll
        for (int e = 0; e < 2; e++) {
            int d = v * 8 + 2 * t4 + e;
            if (qA < 196)
                g_att[((size_t)b * 256 + h * 32 + d) * 196 + qA] = hardswish(oc[v][e] * inv0);
            if (qB < 196)
                g_att[((size_t)b * 256 + h * 32 + d) * 196 + qB] = hardswish(oc[v][2 + e] * inv1);
        }
    }
}

// ---------------- launch -----------------------------------------------------
extern "C" void kernel_launch(void* const* d_in, const int* in_sizes, int n_in,
                              void* d_out, int out_size)
{
    const float* x      = (const float*)d_in[0];
    const float* kv_w   = (const float*)d_in[1];
    const float* kv_g   = (const float*)d_in[2];
    const float* kv_b   = (const float*)d_in[3];
    const float* kv_m   = (const float*)d_in[4];
    const float* kv_v   = (const float*)d_in[5];
    const float* q_w    = (const float*)d_in[6];
    const float* q_g    = (const float*)d_in[7];
    const float* q_b    = (const float*)d_in[8];
    const float* q_m    = (const float*)d_in[9];
    const float* q_v    = (const float*)d_in[10];
    const float* proj_w = (const float*)d_in[11];
    const float* proj_g = (const float*)d_in[12];
    const float* proj_b = (const float*)d_in[13];
    const float* proj_m = (const float*)d_in[14];
    const float* proj_v = (const float*)d_in[15];
    const float* ab     = (const float*)d_in[16];
    const int*   idxs   = (const int*)  d_in[17];
    const int n_off = in_sizes[16] / 8;

    float* out = (float*)d_out;

    float *p_kv, *p_q, *p_att;
    cudaGetSymbolAddress((void**)&p_kv,  g_kv);
    cudaGetSymbolAddress((void**)&p_q,   g_q);
    cudaGetSymbolAddress((void**)&p_att, g_att);

    // 1) bias table [h][q][m], *log2e
    bias_gather_kernel<<<dim3(196, 8), 784>>>(ab, idxs, n_off);

    // 2) kv: cols = 64*784 = 50176 = 392*128
    conv_bn_hsw_tc_kernel<false><<<dim3(3, 392), 256>>>(
        x, 256 * 784, 784, kv_w, 256, kv_g, kv_b, kv_m, kv_v, p_kv, 384, 784);

    // 3) q: cols = 64*196 = 12544 = 98*128 (strided input gather)
    conv_bn_hsw_tc_kernel<true><<<dim3(1, 98), 256>>>(
        x, 256 * 784, 784, q_w, 256, q_g, q_b, q_m, q_v, p_q, 128, 196);

    // 4) tensor-core flash attention -> g_att (with pre-proj hardswish)
    attention_tc_kernel<<<dim3(512, 4), 128>>>();

    // 5) proj: cols = 64*196 = 12544 = 98*128
    conv_bn_hsw_tc_kernel<false><<<dim3(4, 98), 256>>>(
        p_att, 256 * 196, 196, proj_w, 256, proj_g, proj_b, proj_m, proj_v, out, 512, 196);
}

// round 9
// speedup vs baseline: 1.5808x; 1.1860x over previous
#include <cuda_runtime.h>
#include <cuda_fp16.h>
#include <math.h>
#include <stdint.h>

#define BN_EPS 1e-5f
#define LOG2E 1.4426950408889634f

// ---------------- scratch (static device buffers; no allocations) ----------
__device__ float  g_kv  [64u*384u*784u];  // kv conv output  [b][o=384][n=784]
__device__ float  g_q   [64u*128u*196u];  // q  conv output  [b][o=128][n=196]
__device__ __half g_bias[ 8u*196u*784u];  // bias*log2e (fp16) [h][q][m]
__device__ float  g_att [64u*256u*196u];  // hardswish(attn out) [b][c=256][n=196]

__device__ __forceinline__ float hardswish(float x) {
    float t = fminf(fmaxf(x + 3.f, 0.f), 6.f);
    return x * t * (1.f / 6.f);
}

__device__ __forceinline__ uint32_t f2tf32(float x) {
    uint32_t r;
    asm("cvt.rna.tf32.f32 %0, %1;" : "=r"(r) : "f"(x));
    return r;
}

__device__ __forceinline__ uint32_t pack_h2(float lo, float hi) {
    uint32_t r;
    asm("cvt.rn.f16x2.f32 %0, %1, %2;" : "=r"(r) : "f"(hi), "f"(lo));
    return r;
}

__device__ __forceinline__ float exp2fast(float x) {
    float y;
    asm("ex2.approx.f32 %0, %1;" : "=f"(y) : "f"(x));
    return y;
}

__device__ __forceinline__ void mma_tf32(float c[4], const uint32_t a[4],
                                         uint32_t b0, uint32_t b1) {
    asm volatile(
        "mma.sync.aligned.m16n8k8.row.col.f32.tf32.tf32.f32 "
        "{%0,%1,%2,%3}, {%4,%5,%6,%7}, {%8,%9}, {%0,%1,%2,%3};"
        : "+f"(c[0]), "+f"(c[1]), "+f"(c[2]), "+f"(c[3])
        : "r"(a[0]), "r"(a[1]), "r"(a[2]), "r"(a[3]), "r"(b0), "r"(b1));
}

__device__ __forceinline__ void mma_f16_k16(float c[4], const uint32_t a[4],
                                            uint32_t b0, uint32_t b1) {
    asm volatile(
        "mma.sync.aligned.m16n8k16.row.col.f32.f16.f16.f32 "
        "{%0,%1,%2,%3}, {%4,%5,%6,%7}, {%8,%9}, {%0,%1,%2,%3};"
        : "+f"(c[0]), "+f"(c[1]), "+f"(c[2]), "+f"(c[3])
        : "r"(a[0]), "r"(a[1]), "r"(a[2]), "r"(a[3]), "r"(b0), "r"(b1));
}

__device__ __forceinline__ void mma_f16_k8(float c[4], uint32_t a0, uint32_t a1,
                                           uint32_t b0) {
    asm volatile(
        "mma.sync.aligned.m16n8k8.row.col.f32.f16.f16.f32 "
        "{%0,%1,%2,%3}, {%4,%5}, {%6}, {%0,%1,%2,%3};"
        : "+f"(c[0]), "+f"(c[1]), "+f"(c[2]), "+f"(c[3])
        : "r"(a0), "r"(a1), "r"(b0));
}

// ---------------- bias gather: g_bias[h][q][m] = half(ab[...] * log2e) -----
__global__ void bias_gather_kernel(const float* __restrict__ ab,
                                   const int*   __restrict__ idxs,
                                   int n_off)
{
    int q = blockIdx.x;
    int h = blockIdx.y;
    int m = threadIdx.x;
    int idx = idxs[q * 784 + m];
    g_bias[((size_t)h * 196 + q) * 784 + m] = __float2half(ab[h * n_off + idx] * LOG2E);
}

// ---------------- TF32 GEMM + BN + hardswish, batch-flattened N -------------
template<bool STRIDED>
__global__ void __launch_bounds__(256, 2)
conv_bn_hsw_tc_kernel(const float* __restrict__ X, int xbs, int ldx,
                      const float* __restrict__ W, int C,
                      const float* __restrict__ gam, const float* __restrict__ bet,
                      const float* __restrict__ mu,  const float* __restrict__ var,
                      float* __restrict__ Y, int O, int NperB)
{
    __shared__ uint32_t As[2][128][20];
    __shared__ uint32_t Bs[2][128][20];

    const int o0 = blockIdx.x * 128;
    const int n0 = blockIdx.y * 128;
    const int t  = threadIdx.x;

    const int warp = t >> 5;
    const int lane = t & 31;
    const int g    = lane >> 2;
    const int t4   = lane & 3;
    const int wm   = warp >> 2;
    const int wn   = warp & 3;
    const int mrow0 = wm * 64;
    const int ncol0 = wn * 32;

    const int arow0 = t >> 2, aseg = t & 3;
    const int bcol = t & 127;
    const int bks  = t >> 7;
    const int colg = n0 + bcol;
    const int bb   = colg / NperB;
    int nn = colg - bb * NperB;
    if (STRIDED) nn = 2 * (nn / 14) * 28 + 2 * (nn % 14);
    const float* bsrc = X + (size_t)bb * xbs + nn;

    float acc[4][4][4];
    #pragma unroll
    for (int i = 0; i < 4; i++)
        #pragma unroll
        for (int j = 0; j < 4; j++)
            #pragma unroll
            for (int e = 0; e < 4; e++) acc[i][j][e] = 0.f;

    float4 avr[2];
    float  bvr[8];

    #pragma unroll
    for (int r = 0; r < 2; r++)
        avr[r] = *reinterpret_cast<const float4*>(&W[(o0 + arow0 + r * 64) * C + aseg * 4]);
    #pragma unroll
    for (int j = 0; j < 8; j++)
        bvr[j] = bsrc[(size_t)(bks * 8 + j) * ldx];

    #pragma unroll
    for (int r = 0; r < 2; r++) {
        int row = arow0 + r * 64;
        uint4 w = make_uint4(f2tf32(avr[r].x), f2tf32(avr[r].y),
                             f2tf32(avr[r].z), f2tf32(avr[r].w));
        *reinterpret_cast<uint4*>(&As[0][row][aseg * 4]) = w;
    }
    {
        uint4 w0 = make_uint4(f2tf32(bvr[0]), f2tf32(bvr[1]), f2tf32(bvr[2]), f2tf32(bvr[3]));
        uint4 w1 = make_uint4(f2tf32(bvr[4]), f2tf32(bvr[5]), f2tf32(bvr[6]), f2tf32(bvr[7]));
        *reinterpret_cast<uint4*>(&Bs[0][bcol][bks * 8 + 0]) = w0;
        *reinterpret_cast<uint4*>(&Bs[0][bcol][bks * 8 + 4]) = w1;
    }
    __syncthreads();

    int buf = 0;
    const int nslab = C >> 4;
    for (int s = 0; s < nslab; s++) {
        const bool more = (s + 1 < nslab);
        const int c1 = (s + 1) << 4;
        if (more) {
            #pragma unroll
            for (int r = 0; r < 2; r++)
                avr[r] = *reinterpret_cast<const float4*>(
                    &W[(o0 + arow0 + r * 64) * C + c1 + aseg * 4]);
            #pragma unroll
            for (int j = 0; j < 8; j++)
                bvr[j] = bsrc[(size_t)(c1 + bks * 8 + j) * ldx];
        }

        #pragma unroll
        for (int ks = 0; ks < 16; ks += 8) {
            uint32_t a[4][4];
            #pragma unroll
            for (int mf = 0; mf < 4; mf++) {
                int rb = mrow0 + mf * 16;
                a[mf][0] = As[buf][rb + g    ][ks + t4    ];
                a[mf][1] = As[buf][rb + g + 8][ks + t4    ];
                a[mf][2] = As[buf][rb + g    ][ks + t4 + 4];
                a[mf][3] = As[buf][rb + g + 8][ks + t4 + 4];
            }
            uint32_t bfr[4][2];
            #pragma unroll
            for (int nf = 0; nf < 4; nf++) {
                int cb = ncol0 + nf * 8;
                bfr[nf][0] = Bs[buf][cb + g][ks + t4    ];
                bfr[nf][1] = Bs[buf][cb + g][ks + t4 + 4];
            }
            #pragma unroll
            for (int mf = 0; mf < 4; mf++)
                #pragma unroll
                for (int nf = 0; nf < 4; nf++)
                    mma_tf32(acc[mf][nf], a[mf], bfr[nf][0], bfr[nf][1]);
        }

        if (more) {
            int nb = buf ^ 1;
            #pragma unroll
            for (int r = 0; r < 2; r++) {
                int row = arow0 + r * 64;
                uint4 w = make_uint4(f2tf32(avr[r].x), f2tf32(avr[r].y),
                                     f2tf32(avr[r].z), f2tf32(avr[r].w));
                *reinterpret_cast<uint4*>(&As[nb][row][aseg * 4]) = w;
            }
            uint4 w0 = make_uint4(f2tf32(bvr[0]), f2tf32(bvr[1]), f2tf32(bvr[2]), f2tf32(bvr[3]));
            uint4 w1 = make_uint4(f2tf32(bvr[4]), f2tf32(bvr[5]), f2tf32(bvr[6]), f2tf32(bvr[7]));
            *reinterpret_cast<uint4*>(&Bs[nb][bcol][bks * 8 + 0]) = w0;
            *reinterpret_cast<uint4*>(&Bs[nb][bcol][bks * 8 + 4]) = w1;
        }
        __syncthreads();
        buf ^= 1;
    }

    int ecb[8]; int ecn[8];
    #pragma unroll
    for (int nf = 0; nf < 4; nf++) {
        #pragma unroll
        for (int e = 0; e < 2; e++) {
            int idx = nf * 2 + e;
            int col = n0 + ncol0 + nf * 8 + t4 * 2 + e;
            int cb2 = col / NperB;
            ecb[idx] = cb2;
            ecn[idx] = col - cb2 * NperB;
        }
    }
    #pragma unroll
    for (int mf = 0; mf < 4; mf++) {
        #pragma unroll
        for (int half = 0; half < 2; half++) {
            int o = o0 + mrow0 + mf * 16 + g + half * 8;
            float sc = gam[o] * rsqrtf(var[o] + BN_EPS);
            float mm = mu[o], bt = bet[o];
            #pragma unroll
            for (int nf = 0; nf < 4; nf++) {
                #pragma unroll
                for (int e = 0; e < 2; e++) {
                    int idx = nf * 2 + e;
                    float y = (acc[mf][nf][half * 2 + e] - mm) * sc + bt;
                    Y[((size_t)ecb[idx] * O + o) * NperB + ecn[idx]] = hardswish(y);
                }
            }
        }
    }
}

// ---------------- fp16 tensor-core flash attention ---------------------------
// grid (512 bh, 4 qblocks), 128 threads / 4 warps, 16 queries per warp.
// QK via m16n8k16 f16 (K packed half2 in smem), P kept in registers and fed
// directly as the A operand of PV (m16n8k16 + k8 tail). No P smem round-trip.
__global__ void __launch_bounds__(128)
attention_tc_kernel()
{
    const int bh = blockIdx.x;
    const int b = bh >> 3, h = bh & 7;
    const int qb = blockIdx.y;
    const int t = threadIdx.x;
    const int warp = t >> 5, lane = t & 31;
    const int g = lane >> 2, t4 = lane & 3;

    // Ks[m][pair-perm]: pair p packs K[m][2p],K[m][2p+1]; phys = (p&3)*2+(p>>2)
    // pitch 8 pairs (exact). Vs[d][pair-perm], 28 pairs, pitch 40, perm within 8-groups.
    __shared__ uint32_t Ks[56 * 8];
    __shared__ uint32_t Vs[32 * 40];

    const float* kvb = g_kv + ((size_t)b * 384 + (size_t)h * 48) * 784;
    const __half* bsh = g_bias + (size_t)h * 196 * 784;

    // staging thread coordinates (bank-exact)
    const int sm_ = (t & 3) + ((t >> 5) << 2);   // 0..15
    const int sp_ = (t >> 2) & 7;                // 0..7
    const int sphys = ((sp_ & 3) << 1) + (sp_ >> 2);

    const int q0 = qb * 64 + warp * 16;
    const int qA = q0 + g, qB = q0 + g + 8;

    // Q fragment for m16n8k16: a0=qA d[2t4,2t4+1], a1=qB same, a2=qA d+8, a3=qB d+8
    uint32_t qh[4];
    {
        const float QS = 0.25f * LOG2E;
        float qa0 = 0.f, qa1 = 0.f, qa8 = 0.f, qa9 = 0.f;
        float qb0 = 0.f, qb1 = 0.f, qb8 = 0.f, qb9 = 0.f;
        const float* qbase = g_q + (size_t)b * 128 * 196 + (size_t)h * 16 * 196;
        if (qA < 196) {
            qa0 = qbase[(2 * t4    ) * 196 + qA] * QS;
            qa1 = qbase[(2 * t4 + 1) * 196 + qA] * QS;
            qa8 = qbase[(2 * t4 + 8) * 196 + qA] * QS;
            qa9 = qbase[(2 * t4 + 9) * 196 + qA] * QS;
        }
        if (qB < 196) {
            qb0 = qbase[(2 * t4    ) * 196 + qB] * QS;
            qb1 = qbase[(2 * t4 + 1) * 196 + qB] * QS;
            qb8 = qbase[(2 * t4 + 8) * 196 + qB] * QS;
            qb9 = qbase[(2 * t4 + 9) * 196 + qB] * QS;
        }
        qh[0] = pack_h2(qa0, qa1);
        qh[1] = pack_h2(qb0, qb1);
        qh[2] = pack_h2(qa8, qa9);
        qh[3] = pack_h2(qb8, qb9);
    }

    float oc[4][4];
    #pragma unroll
    for (int v = 0; v < 4; v++)
        #pragma unroll
        for (int e = 0; e < 4; e++) oc[v][e] = 0.f;
    float rm0 = -1e30f, rm1 = -1e30f, rl0 = 0.f, rl1 = 0.f;

    for (int m0 = 0; m0 < 784; m0 += 56) {
        // ---- stage K: 56 m x 8 pairs; thread (sm_, sp_), m advances by 16
        #pragma unroll
        for (int pass = 0; pass < 4; pass++) {
            int m = sm_ + 16 * pass;
            if (m < 56) {
                float lo = kvb[(size_t)(2 * sp_    ) * 784 + m0 + m];
                float hi = kvb[(size_t)(2 * sp_ + 1) * 784 + m0 + m];
                Ks[m * 8 + sphys] = pack_h2(lo, hi);
            }
        }
        // ---- stage V: 32 d x 28 pairs; pair l packs V[d][2l],V[d][2l+1]
        #pragma unroll
        for (int dp = 0; dp < 2; dp++) {
            int d = sm_ + 16 * dp;
            const float* vrow = kvb + (size_t)(16 + d) * 784 + m0;
            #pragma unroll
            for (int lp = 0; lp < 4; lp++) {
                int l = sp_ + 8 * lp;
                if (l < 28) {
                    float lo = vrow[2 * l];
                    float hi = vrow[2 * l + 1];
                    int phys = ((l >> 3) << 3) + (((l & 3) << 1) + ((l & 7) >> 2));
                    Vs[d * 40 + phys] = pack_h2(lo, hi);
                }
            }
        }
        __syncthreads();

        // ---- S = bias + Q K^T  (7 k16 mmas)
        float sc[7][4];
        #pragma unroll
        for (int j = 0; j < 7; j++) {
            int m = m0 + j * 8 + 2 * t4;
            if (qA < 196) {
                __half2 bv = *reinterpret_cast<const __half2*>(&bsh[(size_t)qA * 784 + m]);
                float2 bf = __half22float2(bv);
                sc[j][0] = bf.x; sc[j][1] = bf.y;
            } else { sc[j][0] = 0.f; sc[j][1] = 0.f; }
            if (qB < 196) {
                __half2 bv = *reinterpret_cast<const __half2*>(&bsh[(size_t)qB * 784 + m]);
                float2 bf = __half22float2(bv);
                sc[j][2] = bf.x; sc[j][3] = bf.y;
            } else { sc[j][2] = 0.f; sc[j][3] = 0.f; }
        }
        #pragma unroll
        for (int j = 0; j < 7; j++) {
            uint2 kk = *reinterpret_cast<const uint2*>(&Ks[(j * 8 + g) * 8 + 2 * t4]);
            mma_f16_k16(sc[j], qh, kk.x, kk.y);
        }

        // ---- online softmax (exp2 domain)
        float mx0 = rm0, mx1 = rm1;
        #pragma unroll
        for (int j = 0; j < 7; j++) {
            mx0 = fmaxf(mx0, fmaxf(sc[j][0], sc[j][1]));
            mx1 = fmaxf(mx1, fmaxf(sc[j][2], sc[j][3]));
        }
        mx0 = fmaxf(mx0, __shfl_xor_sync(0xffffffffu, mx0, 1));
        mx0 = fmaxf(mx0, __shfl_xor_sync(0xffffffffu, mx0, 2));
        mx1 = fmaxf(mx1, __shfl_xor_sync(0xffffffffu, mx1, 1));
        mx1 = fmaxf(mx1, __shfl_xor_sync(0xffffffffu, mx1, 2));

        float a0 = exp2fast(rm0 - mx0), a1 = exp2fast(rm1 - mx1);
        rl0 *= a0; rl1 *= a1; rm0 = mx0; rm1 = mx1;
        #pragma unroll
        for (int v = 0; v < 4; v++) {
            oc[v][0] *= a0; oc[v][1] *= a0;
            oc[v][2] *= a1; oc[v][3] *= a1;
        }

        // ---- P in registers (packed half2, A-fragment layout)
        uint32_t ph[7][2];
        float s0 = 0.f, s1 = 0.f;
        #pragma unroll
        for (int j = 0; j < 7; j++) {
            float p0 = exp2fast(sc[j][0] - mx0);
            float p1 = exp2fast(sc[j][1] - mx0);
            float p2 = exp2fast(sc[j][2] - mx1);
            float p3 = exp2fast(sc[j][3] - mx1);
            s0 += p0 + p1; s1 += p2 + p3;
            ph[j][0] = pack_h2(p0, p1);
            ph[j][1] = pack_h2(p2, p3);
        }
        s0 += __shfl_xor_sync(0xffffffffu, s0, 1);
        s0 += __shfl_xor_sync(0xffffffffu, s0, 2);
        s1 += __shfl_xor_sync(0xffffffffu, s1, 1);
        s1 += __shfl_xor_sync(0xffffffffu, s1, 2);
        rl0 += s0; rl1 += s1;

        // ---- out += P @ V^T : 3 k16 + 1 k8 per d-group
        #pragma unroll
        for (int jj = 0; jj < 3; jj++) {
            uint32_t pa[4] = { ph[2*jj][0], ph[2*jj][1], ph[2*jj+1][0], ph[2*jj+1][1] };
            #pragma unroll
            for (int v = 0; v < 4; v++) {
                uint2 vv = *reinterpret_cast<const uint2*>(
                    &Vs[(v * 8 + g) * 40 + 8 * jj + 2 * t4]);
                mma_f16_k16(oc[v], pa, vv.x, vv.y);
            }
        }
        #pragma unroll
        for (int v = 0; v < 4; v++) {
            uint32_t vv = Vs[(v * 8 + g) * 40 + 24 + 2 * t4];
            mma_f16_k8(oc[v], ph[6][0], ph[6][1], vv);
        }
        __syncthreads();
    }

    // ---- normalize, hardswish, store
    float inv0 = 1.f / rl0, inv1 = 1.f / rl1;
    #pragma unroll
    for (int v = 0; v < 4; v++) {
        #pragma unroll
        for (int e = 0; e < 2; e++) {
            int d = v * 8 + 2 * t4 + e;
            if (qA < 196)
                g_att[((size_t)b * 256 + h * 32 + d) * 196 + qA] = hardswish(oc[v][e] * inv0);
            if (qB < 196)
                g_att[((size_t)b * 256 + h * 32 + d) * 196 + qB] = hardswish(oc[v][2 + e] * inv1);
        }
    }
}

// ---------------- launch -----------------------------------------------------
extern "C" void kernel_launch(void* const* d_in, const int* in_sizes, int n_in,
                              void* d_out, int out_size)
{
    const float* x      = (const float*)d_in[0];
    const float* kv_w   = (const float*)d_in[1];
    const float* kv_g   = (const float*)d_in[2];
    const float* kv_b   = (const float*)d_in[3];
    const float* kv_m   = (const float*)d_in[4];
    const float* kv_v   = (const float*)d_in[5];
    const float* q_w    = (const float*)d_in[6];
    const float* q_g    = (const float*)d_in[7];
    const float* q_b    = (const float*)d_in[8];
    const float* q_m    = (const float*)d_in[9];
    const float* q_v    = (const float*)d_in[10];
    const float* proj_w = (const float*)d_in[11];
    const float* proj_g = (const float*)d_in[12];
    const float* proj_b = (const float*)d_in[13];
    const float* proj_m = (const float*)d_in[14];
    const float* proj_v = (const float*)d_in[15];
    const float* ab     = (const float*)d_in[16];
    const int*   idxs   = (const int*)  d_in[17];
    const int n_off = in_sizes[16] / 8;

    float* out = (float*)d_out;

    float *p_kv, *p_q, *p_att;
    cudaGetSymbolAddress((void**)&p_kv,  g_kv);
    cudaGetSymbolAddress((void**)&p_q,   g_q);
    cudaGetSymbolAddress((void**)&p_att, g_att);

    // 1) bias table [h][q][m] (fp16, *log2e)
    bias_gather_kernel<<<dim3(196, 8), 784>>>(ab, idxs, n_off);

    // 2) kv: cols = 64*784 = 50176 = 392*128
    conv_bn_hsw_tc_kernel<false><<<dim3(3, 392), 256>>>(
        x, 256 * 784, 784, kv_w, 256, kv_g, kv_b, kv_m, kv_v, p_kv, 384, 784);

    // 3) q: cols = 64*196 = 12544 = 98*128 (strided input gather)
    conv_bn_hsw_tc_kernel<true><<<dim3(1, 98), 256>>>(
        x, 256 * 784, 784, q_w, 256, q_g, q_b, q_m, q_v, p_q, 128, 196);

    // 4) fp16 tensor-core flash attention -> g_att (with pre-proj hardswish)
    attention_tc_kernel<<<dim3(512, 4), 128>>>();

    // 5) proj: cols = 64*196 = 12544 = 98*128
    conv_bn_hsw_tc_kernel<false><<<dim3(4, 98), 256>>>(
        p_att, 256 * 196, 196, proj_w, 256, proj_g, proj_b, proj_m, proj_v, out, 512, 196);
}

// round 10
// speedup vs baseline: 1.9310x; 1.2215x over previous
#include <cuda_runtime.h>
#include <cuda_fp16.h>
#include <math.h>
#include <stdint.h>

#define BN_EPS 1e-5f
#define LOG2E 1.4426950408889634f

// ---------------- scratch (static device buffers; no allocations) ----------
__device__ __half g_kv  [64u*384u*784u];  // kv conv output (fp16) [b][o][n]
__device__ __half g_q   [64u*128u*196u];  // q  conv output (fp16) [b][o][n]
__device__ __half g_bias[ 8u*196u*784u];  // bias*log2e (fp16) [h][q][m]
__device__ __half g_att [64u*256u*196u];  // hardswish(attn out) (fp16) [b][c][n]

__device__ __forceinline__ float hardswish(float x) {
    float t = fminf(fmaxf(x + 3.f, 0.f), 6.f);
    return x * t * (1.f / 6.f);
}

__device__ __forceinline__ uint32_t pack_h2(float lo, float hi) {
    uint32_t r;
    asm("cvt.rn.f16x2.f32 %0, %1, %2;" : "=r"(r) : "f"(hi), "f"(lo));
    return r;
}

__device__ __forceinline__ uint32_t combine_h2(__half lo, __half hi) {
    return (uint32_t)__half_as_ushort(lo) | ((uint32_t)__half_as_ushort(hi) << 16);
}

__device__ __forceinline__ float exp2fast(float x) {
    float y;
    asm("ex2.approx.f32 %0, %1;" : "=f"(y) : "f"(x));
    return y;
}

__device__ __forceinline__ void mma_f16_k16(float c[4], const uint32_t a[4],
                                            uint32_t b0, uint32_t b1) {
    asm volatile(
        "mma.sync.aligned.m16n8k16.row.col.f32.f16.f16.f32 "
        "{%0,%1,%2,%3}, {%4,%5,%6,%7}, {%8,%9}, {%0,%1,%2,%3};"
        : "+f"(c[0]), "+f"(c[1]), "+f"(c[2]), "+f"(c[3])
        : "r"(a[0]), "r"(a[1]), "r"(a[2]), "r"(a[3]), "r"(b0), "r"(b1));
}

__device__ __forceinline__ void mma_f16_k8(float c[4], uint32_t a0, uint32_t a1,
                                           uint32_t b0) {
    asm volatile(
        "mma.sync.aligned.m16n8k8.row.col.f32.f16.f16.f32 "
        "{%0,%1,%2,%3}, {%4,%5}, {%6}, {%0,%1,%2,%3};"
        : "+f"(c[0]), "+f"(c[1]), "+f"(c[2]), "+f"(c[3])
        : "r"(a0), "r"(a1), "r"(b0));
}

__device__ __forceinline__ float ld_in(const float* p)  { return *p; }
__device__ __forceinline__ float ld_in(const __half* p) { return __half2float(*p); }

__device__ __forceinline__ void st_pair(float* p, float y0, float y1) {
    *reinterpret_cast<float2*>(p) = make_float2(y0, y1);
}
__device__ __forceinline__ void st_pair(__half* p, float y0, float y1) {
    *reinterpret_cast<__half2*>(p) = __floats2half2_rn(y0, y1);
}

// pair permutation within groups of 8: phys = (p&3)*2 + (p>>2)
__device__ __forceinline__ int pperm(int p) { return ((p & 3) << 1) + (p >> 2); }

// ---------------- bias gather: g_bias[h][q][m] = half(ab[...] * log2e) -----
__global__ void bias_gather_kernel(const float* __restrict__ ab,
                                   const int*   __restrict__ idxs,
                                   int n_off)
{
    int q = blockIdx.x;
    int h = blockIdx.y;
    int m = threadIdx.x;
    int idx = idxs[q * 784 + m];
    g_bias[((size_t)h * 196 + q) * 784 + m] = __float2half(ab[h * n_off + idx] * LOG2E);
}

// ---------------- fp16 GEMM + BN + hardswish, batch-flattened N -------------
// Y[b][o][n] = hardswish( (sum_c W[o][c]*X[b][c][col(n)] - mu[o])*sc[o]+bt[o] )
// Block 128(O) x 128(cols), 8 warps (2x4), warp tile 64x32, K-slab 16,
// one m16n8k16 step per slab, double-buffered. Smem stores packed half2
// pairs with pperm so every fragment is one LDS.64. Pitch 10 dwords.
template<bool STRIDED, typename IN_T, typename OUT_T>
__global__ void __launch_bounds__(256, 2)
conv_bn_hsw_tc_kernel(const IN_T* __restrict__ X, int xbs, int ldx,
                      const float* __restrict__ W, int C,
                      const float* __restrict__ gam, const float* __restrict__ bet,
                      const float* __restrict__ mu,  const float* __restrict__ var,
                      OUT_T* __restrict__ Y, int O, int NperB)
{
    __shared__ uint32_t As[2][128][10];
    __shared__ uint32_t Bs[2][128][10];

    const int o0 = blockIdx.x * 128;
    const int n0 = blockIdx.y * 128;
    const int t  = threadIdx.x;

    const int warp = t >> 5;
    const int lane = t & 31;
    const int g    = lane >> 2;
    const int t4   = lane & 3;
    const int wm   = warp >> 2;
    const int wn   = warp & 3;
    const int mrow0 = wm * 64;
    const int ncol0 = wn * 32;

    const int arow0 = t >> 2, aseg = t & 3;
    const int aph0 = pperm(2 * aseg), aph1 = pperm(2 * aseg + 1);
    const int bcol = t & 127;
    const int bks  = t >> 7;
    const int colg = n0 + bcol;
    const int bb   = colg / NperB;
    int nn = colg - bb * NperB;
    if (STRIDED) nn = 2 * (nn / 14) * 28 + 2 * (nn % 14);
    const IN_T* bsrc = X + (size_t)bb * xbs + nn;

    float acc[4][4][4];
    #pragma unroll
    for (int i = 0; i < 4; i++)
        #pragma unroll
        for (int j = 0; j < 4; j++)
            #pragma unroll
            for (int e = 0; e < 4; e++) acc[i][j][e] = 0.f;

    float4 avr[2];
    float  bvr[8];

    #pragma unroll
    for (int r = 0; r < 2; r++)
        avr[r] = *reinterpret_cast<const float4*>(&W[(o0 + arow0 + r * 64) * C + aseg * 4]);
    #pragma unroll
    for (int j = 0; j < 8; j++)
        bvr[j] = ld_in(bsrc + (size_t)(bks * 8 + j) * ldx);

    #pragma unroll
    for (int r = 0; r < 2; r++) {
        int row = arow0 + r * 64;
        As[0][row][aph0] = pack_h2(avr[r].x, avr[r].y);
        As[0][row][aph1] = pack_h2(avr[r].z, avr[r].w);
    }
    #pragma unroll
    for (int jj = 0; jj < 4; jj++)
        Bs[0][bcol][pperm(bks * 4 + jj)] = pack_h2(bvr[2 * jj], bvr[2 * jj + 1]);
    __syncthreads();

    int buf = 0;
    const int nslab = C >> 4;
    for (int s = 0; s < nslab; s++) {
        const bool more = (s + 1 < nslab);
        const int c1 = (s + 1) << 4;
        if (more) {
            #pragma unroll
            for (int r = 0; r < 2; r++)
                avr[r] = *reinterpret_cast<const float4*>(
                    &W[(o0 + arow0 + r * 64) * C + c1 + aseg * 4]);
            #pragma unroll
            for (int j = 0; j < 8; j++)
                bvr[j] = ld_in(bsrc + (size_t)(c1 + bks * 8 + j) * ldx);
        }

        // ---- compute slab s: one k16 step
        {
            uint32_t a[4][4];
            #pragma unroll
            for (int mf = 0; mf < 4; mf++) {
                int rb = mrow0 + mf * 16;
                uint2 lo = *reinterpret_cast<const uint2*>(&As[buf][rb + g    ][2 * t4]);
                uint2 hi = *reinterpret_cast<const uint2*>(&As[buf][rb + g + 8][2 * t4]);
                a[mf][0] = lo.x; a[mf][1] = hi.x; a[mf][2] = lo.y; a[mf][3] = hi.y;
            }
            uint2 bfr[4];
            #pragma unroll
            for (int nf = 0; nf < 4; nf++)
                bfr[nf] = *reinterpret_cast<const uint2*>(&Bs[buf][ncol0 + nf * 8 + g][2 * t4]);
            #pragma unroll
            for (int mf = 0; mf < 4; mf++)
                #pragma unroll
                for (int nf = 0; nf < 4; nf++)
                    mma_f16_k16(acc[mf][nf], a[mf], bfr[nf].x, bfr[nf].y);
        }

        if (more) {
            int nb = buf ^ 1;
            #pragma unroll
            for (int r = 0; r < 2; r++) {
                int row = arow0 + r * 64;
                As[nb][row][aph0] = pack_h2(avr[r].x, avr[r].y);
                As[nb][row][aph1] = pack_h2(avr[r].z, avr[r].w);
            }
            #pragma unroll
            for (int jj = 0; jj < 4; jj++)
                Bs[nb][bcol][pperm(bks * 4 + jj)] = pack_h2(bvr[2 * jj], bvr[2 * jj + 1]);
        }
        __syncthreads();
        buf ^= 1;
    }

    // ---- epilogue: BN + hardswish, paired stores
    int ecb[4]; int ecn[4];
    #pragma unroll
    for (int nf = 0; nf < 4; nf++) {
        int col = n0 + ncol0 + nf * 8 + t4 * 2;
        int cb2 = col / NperB;
        ecb[nf] = cb2;
        ecn[nf] = col - cb2 * NperB;
    }
    #pragma unroll
    for (int mf = 0; mf < 4; mf++) {
        #pragma unroll
        for (int half = 0; half < 2; half++) {
            int o = o0 + mrow0 + mf * 16 + g + half * 8;
            float sc = gam[o] * rsqrtf(var[o] + BN_EPS);
            float mm = mu[o], bt = bet[o];
            #pragma unroll
            for (int nf = 0; nf < 4; nf++) {
                float y0 = (acc[mf][nf][half * 2 + 0] - mm) * sc + bt;
                float y1 = (acc[mf][nf][half * 2 + 1] - mm) * sc + bt;
                st_pair(Y + ((size_t)ecb[nf] * O + o) * NperB + ecn[nf],
                        hardswish(y0), hardswish(y1));
            }
        }
    }
}

// ---------------- fp16 tensor-core flash attention ---------------------------
// grid (512 bh, 4 qblocks), 128 threads / 4 warps, 16 queries per warp.
__global__ void __launch_bounds__(128)
attention_tc_kernel()
{
    const int bh = blockIdx.x;
    const int b = bh >> 3, h = bh & 7;
    const int qb = blockIdx.y;
    const int t = threadIdx.x;
    const int warp = t >> 5, lane = t & 31;
    const int g = lane >> 2, t4 = lane & 3;

    __shared__ uint32_t Ks[56 * 8];    // [m][d-pair perm], pitch 8 (exact)
    __shared__ uint32_t Vs[32 * 40];   // [d][m-pair perm], pitch 40

    const __half* kvb = g_kv + ((size_t)b * 384 + (size_t)h * 48) * 784;
    const __half* bsh = g_bias + (size_t)h * 196 * 784;

    const int sm_ = (t & 3) + ((t >> 5) << 2);   // 0..15
    const int sp_ = (t >> 2) & 7;                // 0..7
    const int sphys = ((sp_ & 3) << 1) + (sp_ >> 2);

    const int q0 = qb * 64 + warp * 16;
    const int qA = q0 + g, qB = q0 + g + 8;

    uint32_t qh[4];
    {
        const float QS = 0.25f * LOG2E;
        float qa0 = 0.f, qa1 = 0.f, qa8 = 0.f, qa9 = 0.f;
        float qb0 = 0.f, qb1 = 0.f, qb8 = 0.f, qb9 = 0.f;
        const __half* qbase = g_q + (size_t)b * 128 * 196 + (size_t)h * 16 * 196;
        if (qA < 196) {
            qa0 = __half2float(qbase[(2 * t4    ) * 196 + qA]) * QS;
            qa1 = __half2float(qbase[(2 * t4 + 1) * 196 + qA]) * QS;
            qa8 = __half2float(qbase[(2 * t4 + 8) * 196 + qA]) * QS;
            qa9 = __half2float(qbase[(2 * t4 + 9) * 196 + qA]) * QS;
        }
        if (qB < 196) {
            qb0 = __half2float(qbase[(2 * t4    ) * 196 + qB]) * QS;
            qb1 = __half2float(qbase[(2 * t4 + 1) * 196 + qB]) * QS;
            qb8 = __half2float(qbase[(2 * t4 + 8) * 196 + qB]) * QS;
            qb9 = __half2float(qbase[(2 * t4 + 9) * 196 + qB]) * QS;
        }
        qh[0] = pack_h2(qa0, qa1);
        qh[1] = pack_h2(qb0, qb1);
        qh[2] = pack_h2(qa8, qa9);
        qh[3] = pack_h2(qb8, qb9);
    }

    float oc[4][4];
    #pragma unroll
    for (int v = 0; v < 4; v++)
        #pragma unroll
        for (int e = 0; e < 4; e++) oc[v][e] = 0.f;
    float rm0 = -1e30f, rm1 = -1e30f, rl0 = 0.f, rl1 = 0.f;

    for (int m0 = 0; m0 < 784; m0 += 56) {
        // ---- stage K: pairs along d (two rows), combined without cvt
        #pragma unroll
        for (int pass = 0; pass < 4; pass++) {
            int m = sm_ + 16 * pass;
            if (m < 56) {
                __half lo = kvb[(size_t)(2 * sp_    ) * 784 + m0 + m];
                __half hi = kvb[(size_t)(2 * sp_ + 1) * 784 + m0 + m];
                Ks[m * 8 + sphys] = combine_h2(lo, hi);
            }
        }
        // ---- stage V: pairs along m are adjacent -> single 32-bit loads
        #pragma unroll
        for (int dp = 0; dp < 2; dp++) {
            int d = sm_ + 16 * dp;
            const __half* vrow = kvb + (size_t)(16 + d) * 784 + m0;
            #pragma unroll
            for (int lp = 0; lp < 4; lp++) {
                int l = sp_ + 8 * lp;
                if (l < 28) {
                    uint32_t pv = *reinterpret_cast<const uint32_t*>(&vrow[2 * l]);
                    int phys = ((l >> 3) << 3) + (((l & 3) << 1) + ((l & 7) >> 2));
                    Vs[d * 40 + phys] = pv;
                }
            }
        }
        __syncthreads();

        // ---- S = bias + Q K^T  (7 k16 mmas)
        float sc[7][4];
        #pragma unroll
        for (int j = 0; j < 7; j++) {
            int m = m0 + j * 8 + 2 * t4;
            if (qA < 196) {
                __half2 bv = *reinterpret_cast<const __half2*>(&bsh[(size_t)qA * 784 + m]);
                float2 bf = __half22float2(bv);
                sc[j][0] = bf.x; sc[j][1] = bf.y;
            } else { sc[j][0] = 0.f; sc[j][1] = 0.f; }
            if (qB < 196) {
                __half2 bv = *reinterpret_cast<const __half2*>(&bsh[(size_t)qB * 784 + m]);
                float2 bf = __half22float2(bv);
                sc[j][2] = bf.x; sc[j][3] = bf.y;
            } else { sc[j][2] = 0.f; sc[j][3] = 0.f; }
        }
        #pragma unroll
        for (int j = 0; j < 7; j++) {
            uint2 kk = *reinterpret_cast<const uint2*>(&Ks[(j * 8 + g) * 8 + 2 * t4]);
            mma_f16_k16(sc[j], qh, kk.x, kk.y);
        }

        // ---- online softmax (exp2 domain)
        float mx0 = rm0, mx1 = rm1;
        #pragma unroll
        for (int j = 0; j < 7; j++) {
            mx0 = fmaxf(mx0, fmaxf(sc[j][0], sc[j][1]));
            mx1 = fmaxf(mx1, fmaxf(sc[j][2], sc[j][3]));
        }
        mx0 = fmaxf(mx0, __shfl_xor_sync(0xffffffffu, mx0, 1));
        mx0 = fmaxf(mx0, __shfl_xor_sync(0xffffffffu, mx0, 2));
        mx1 = fmaxf(mx1, __shfl_xor_sync(0xffffffffu, mx1, 1));
        mx1 = fmaxf(mx1, __shfl_xor_sync(0xffffffffu, mx1, 2));

        float a0 = exp2fast(rm0 - mx0), a1 = exp2fast(rm1 - mx1);
        rl0 *= a0; rl1 *= a1; rm0 = mx0; rm1 = mx1;
        #pragma unroll
        for (int v = 0; v < 4; v++) {
            oc[v][0] *= a0; oc[v][1] *= a0;
            oc[v][2] *= a1; oc[v][3] *= a1;
        }

        uint32_t ph[7][2];
        float s0 = 0.f, s1 = 0.f;
        #pragma unroll
        for (int j = 0; j < 7; j++) {
            float p0 = exp2fast(sc[j][0] - mx0);
            float p1 = exp2fast(sc[j][1] - mx0);
            float p2 = exp2fast(sc[j][2] - mx1);
            float p3 = exp2fast(sc[j][3] - mx1);
            s0 += p0 + p1; s1 += p2 + p3;
            ph[j][0] = pack_h2(p0, p1);
            ph[j][1] = pack_h2(p2, p3);
        }
        s0 += __shfl_xor_sync(0xffffffffu, s0, 1);
        s0 += __shfl_xor_sync(0xffffffffu, s0, 2);
        s1 += __shfl_xor_sync(0xffffffffu, s1, 1);
        s1 += __shfl_xor_sync(0xffffffffu, s1, 2);
        rl0 += s0; rl1 += s1;

        // ---- out += P @ V^T : 3 k16 + 1 k8 per d-group
        #pragma unroll
        for (int jj = 0; jj < 3; jj++) {
            uint32_t pa[4] = { ph[2*jj][0], ph[2*jj][1], ph[2*jj+1][0], ph[2*jj+1][1] };
            #pragma unroll
            for (int v = 0; v < 4; v++) {
                uint2 vv = *reinterpret_cast<const uint2*>(
                    &Vs[(v * 8 + g) * 40 + 8 * jj + 2 * t4]);
                mma_f16_k16(oc[v], pa, vv.x, vv.y);
            }
        }
        #pragma unroll
        for (int v = 0; v < 4; v++) {
            uint32_t vv = Vs[(v * 8 + g) * 40 + 24 + 2 * t4];
            mma_f16_k8(oc[v], ph[6][0], ph[6][1], vv);
        }
        __syncthreads();
    }

    // ---- normalize, hardswish, store (fp16)
    float inv0 = 1.f / rl0, inv1 = 1.f / rl1;
    #pragma unroll
    for (int v = 0; v < 4; v++) {
        #pragma unroll
        for (int e = 0; e < 2; e++) {
            int d = v * 8 + 2 * t4 + e;
            if (qA < 196)
                g_att[((size_t)b * 256 + h * 32 + d) * 196 + qA] =
                    __float2half(hardswish(oc[v][e] * inv0));
            if (qB < 196)
                g_att[((size_t)b * 256 + h * 32 + d) * 196 + qB] =
                    __float2half(hardswish(oc[v][2 + e] * inv1));
        }
    }
}

// ---------------- launch -----------------------------------------------------
extern "C" void kernel_launch(void* const* d_in, const int* in_sizes, int n_in,
                              void* d_out, int out_size)
{
    const float* x      = (const float*)d_in[0];
    const float* kv_w   = (const float*)d_in[1];
    const float* kv_g   = (const float*)d_in[2];
    const float* kv_b   = (const float*)d_in[3];
    const float* kv_m   = (const float*)d_in[4];
    const float* kv_v   = (const float*)d_in[5];
    const float* q_w    = (const float*)d_in[6];
    const float* q_g    = (const float*)d_in[7];
    const float* q_b    = (const float*)d_in[8];
    const float* q_m    = (const float*)d_in[9];
    const float* q_v    = (const float*)d_in[10];
    const float* proj_w = (const float*)d_in[11];
    const float* proj_g = (const float*)d_in[12];
    const float* proj_b = (const float*)d_in[13];
    const float* proj_m = (const float*)d_in[14];
    const float* proj_v = (const float*)d_in[15];
    const float* ab     = (const float*)d_in[16];
    const int*   idxs   = (const int*)  d_in[17];
    const int n_off = in_sizes[16] / 8;

    float* out = (float*)d_out;

    __half *p_kv, *p_q, *p_att;
    cudaGetSymbolAddress((void**)&p_kv,  g_kv);
    cudaGetSymbolAddress((void**)&p_q,   g_q);
    cudaGetSymbolAddress((void**)&p_att, g_att);

    // 1) bias table [h][q][m] (fp16, *log2e)
    bias_gather_kernel<<<dim3(196, 8), 784>>>(ab, idxs, n_off);

    // 2) kv: cols = 64*784 = 50176 = 392*128
    conv_bn_hsw_tc_kernel<false, float, __half><<<dim3(3, 392), 256>>>(
        x, 256 * 784, 784, kv_w, 256, kv_g, kv_b, kv_m, kv_v, p_kv, 384, 784);

    // 3) q: cols = 64*196 = 12544 = 98*128 (strided input gather)
    conv_bn_hsw_tc_kernel<true, float, __half><<<dim3(1, 98), 256>>>(
        x, 256 * 784, 784, q_w, 256, q_g, q_b, q_m, q_v, p_q, 128, 196);

    // 4) fp16 tensor-core flash attention -> g_att (with pre-proj hardswish)
    attention_tc_kernel<<<dim3(512, 4), 128>>>();

    // 5) proj: cols = 64*196 = 12544 = 98*128, fp16 in, fp32 out
    conv_bn_hsw_tc_kernel<false, __half, float><<<dim3(4, 98), 256>>>(
        p_att, 256 * 196, 196, proj_w, 256, proj_g, proj_b, proj_m, proj_v, out, 512, 196);
}

// round 11
// speedup vs baseline: 1.9486x; 1.0091x over previous
#include <cuda_runtime.h>
#include <cuda_fp16.h>
#include <math.h>
#include <stdint.h>

#define BN_EPS 1e-5f
#define LOG2E 1.4426950408889634f

// ---------------- scratch (static device buffers; no allocations) ----------
__device__ __half g_kv  [64u*384u*784u];  // kv conv output (fp16) [b][o][n]
__device__ __half g_q   [64u*128u*196u];  // q  conv output (fp16) [b][o][n]
__device__ __half g_bias[ 8u*196u*784u];  // bias*log2e (fp16) [h][q][m]
__device__ __half g_att [64u*256u*196u];  // hardswish(attn out) (fp16) [b][c][n]

__device__ __forceinline__ float hardswish(float x) {
    float t = fminf(fmaxf(x + 3.f, 0.f), 6.f);
    return x * t * (1.f / 6.f);
}

__device__ __forceinline__ uint32_t pack_h2(float lo, float hi) {
    uint32_t r;
    asm("cvt.rn.f16x2.f32 %0, %1, %2;" : "=r"(r) : "f"(hi), "f"(lo));
    return r;
}

__device__ __forceinline__ uint32_t combine_h2(__half lo, __half hi) {
    return (uint32_t)__half_as_ushort(lo) | ((uint32_t)__half_as_ushort(hi) << 16);
}

__device__ __forceinline__ float exp2fast(float x) {
    float y;
    asm("ex2.approx.f32 %0, %1;" : "=f"(y) : "f"(x));
    return y;
}

__device__ __forceinline__ uint32_t h2exp2(uint32_t x) {
    uint32_t y;
    asm("ex2.approx.f16x2 %0, %1;" : "=r"(y) : "r"(x));
    return y;
}

__device__ __forceinline__ void mma_f16_k16(float c[4], const uint32_t a[4],
                                            uint32_t b0, uint32_t b1) {
    asm volatile(
        "mma.sync.aligned.m16n8k16.row.col.f32.f16.f16.f32 "
        "{%0,%1,%2,%3}, {%4,%5,%6,%7}, {%8,%9}, {%0,%1,%2,%3};"
        : "+f"(c[0]), "+f"(c[1]), "+f"(c[2]), "+f"(c[3])
        : "r"(a[0]), "r"(a[1]), "r"(a[2]), "r"(a[3]), "r"(b0), "r"(b1));
}

__device__ __forceinline__ void mma_f16_k8(float c[4], uint32_t a0, uint32_t a1,
                                           uint32_t b0) {
    asm volatile(
        "mma.sync.aligned.m16n8k8.row.col.f32.f16.f16.f32 "
        "{%0,%1,%2,%3}, {%4,%5}, {%6}, {%0,%1,%2,%3};"
        : "+f"(c[0]), "+f"(c[1]), "+f"(c[2]), "+f"(c[3])
        : "r"(a0), "r"(a1), "r"(b0));
}

__device__ __forceinline__ float ld_in(const float* p)  { return *p; }
__device__ __forceinline__ float ld_in(const __half* p) { return __half2float(*p); }

__device__ __forceinline__ void st_pair(float* p, float y0, float y1) {
    *reinterpret_cast<float2*>(p) = make_float2(y0, y1);
}
__device__ __forceinline__ void st_pair(__half* p, float y0, float y1) {
    *reinterpret_cast<__half2*>(p) = __floats2half2_rn(y0, y1);
}

// pair permutation within groups of 8: phys = (p&3)*2 + (p>>2)
__device__ __forceinline__ int pperm(int p) { return ((p & 3) << 1) + (p >> 2); }

// ---------------- bias gather: g_bias[h][q][m] = half(ab[...] * log2e) -----
__global__ void bias_gather_kernel(const float* __restrict__ ab,
                                   const int*   __restrict__ idxs,
                                   int n_off)
{
    int q = blockIdx.x;
    int h = blockIdx.y;
    int m = threadIdx.x;
    int idx = idxs[q * 784 + m];
    g_bias[((size_t)h * 196 + q) * 784 + m] = __float2half(ab[h * n_off + idx] * LOG2E);
}

// ---------------- fp16 GEMM + BN + hardswish, batch-flattened N -------------
template<bool STRIDED, typename IN_T, typename OUT_T>
__global__ void __launch_bounds__(256, 2)
conv_bn_hsw_tc_kernel(const IN_T* __restrict__ X, int xbs, int ldx,
                      const float* __restrict__ W, int C,
                      const float* __restrict__ gam, const float* __restrict__ bet,
                      const float* __restrict__ mu,  const float* __restrict__ var,
                      OUT_T* __restrict__ Y, int O, int NperB)
{
    __shared__ uint32_t As[2][128][10];
    __shared__ uint32_t Bs[2][128][10];

    const int o0 = blockIdx.x * 128;
    const int n0 = blockIdx.y * 128;
    const int t  = threadIdx.x;

    const int warp = t >> 5;
    const int lane = t & 31;
    const int g    = lane >> 2;
    const int t4   = lane & 3;
    const int wm   = warp >> 2;
    const int wn   = warp & 3;
    const int mrow0 = wm * 64;
    const int ncol0 = wn * 32;

    const int arow0 = t >> 2, aseg = t & 3;
    const int aph0 = pperm(2 * aseg), aph1 = pperm(2 * aseg + 1);
    const int bcol = t & 127;
    const int bks  = t >> 7;
    const int colg = n0 + bcol;
    const int bb   = colg / NperB;
    int nn = colg - bb * NperB;
    if (STRIDED) nn = 2 * (nn / 14) * 28 + 2 * (nn % 14);
    const IN_T* bsrc = X + (size_t)bb * xbs + nn;

    float acc[4][4][4];
    #pragma unroll
    for (int i = 0; i < 4; i++)
        #pragma unroll
        for (int j = 0; j < 4; j++)
            #pragma unroll
            for (int e = 0; e < 4; e++) acc[i][j][e] = 0.f;

    float4 avr[2];
    float  bvr[8];

    #pragma unroll
    for (int r = 0; r < 2; r++)
        avr[r] = *reinterpret_cast<const float4*>(&W[(o0 + arow0 + r * 64) * C + aseg * 4]);
    #pragma unroll
    for (int j = 0; j < 8; j++)
        bvr[j] = ld_in(bsrc + (size_t)(bks * 8 + j) * ldx);

    #pragma unroll
    for (int r = 0; r < 2; r++) {
        int row = arow0 + r * 64;
        As[0][row][aph0] = pack_h2(avr[r].x, avr[r].y);
        As[0][row][aph1] = pack_h2(avr[r].z, avr[r].w);
    }
    #pragma unroll
    for (int jj = 0; jj < 4; jj++)
        Bs[0][bcol][pperm(bks * 4 + jj)] = pack_h2(bvr[2 * jj], bvr[2 * jj + 1]);
    __syncthreads();

    int buf = 0;
    const int nslab = C >> 4;
    for (int s = 0; s < nslab; s++) {
        const bool more = (s + 1 < nslab);
        const int c1 = (s + 1) << 4;
        if (more) {
            #pragma unroll
            for (int r = 0; r < 2; r++)
                avr[r] = *reinterpret_cast<const float4*>(
                    &W[(o0 + arow0 + r * 64) * C + c1 + aseg * 4]);
            #pragma unroll
            for (int j = 0; j < 8; j++)
                bvr[j] = ld_in(bsrc + (size_t)(c1 + bks * 8 + j) * ldx);
        }

        {
            uint32_t a[4][4];
            #pragma unroll
            for (int mf = 0; mf < 4; mf++) {
                int rb = mrow0 + mf * 16;
                uint2 lo = *reinterpret_cast<const uint2*>(&As[buf][rb + g    ][2 * t4]);
                uint2 hi = *reinterpret_cast<const uint2*>(&As[buf][rb + g + 8][2 * t4]);
                a[mf][0] = lo.x; a[mf][1] = hi.x; a[mf][2] = lo.y; a[mf][3] = hi.y;
            }
            uint2 bfr[4];
            #pragma unroll
            for (int nf = 0; nf < 4; nf++)
                bfr[nf] = *reinterpret_cast<const uint2*>(&Bs[buf][ncol0 + nf * 8 + g][2 * t4]);
            #pragma unroll
            for (int mf = 0; mf < 4; mf++)
                #pragma unroll
                for (int nf = 0; nf < 4; nf++)
                    mma_f16_k16(acc[mf][nf], a[mf], bfr[nf].x, bfr[nf].y);
        }

        if (more) {
            int nb = buf ^ 1;
            #pragma unroll
            for (int r = 0; r < 2; r++) {
                int row = arow0 + r * 64;
                As[nb][row][aph0] = pack_h2(avr[r].x, avr[r].y);
                As[nb][row][aph1] = pack_h2(avr[r].z, avr[r].w);
            }
            #pragma unroll
            for (int jj = 0; jj < 4; jj++)
                Bs[nb][bcol][pperm(bks * 4 + jj)] = pack_h2(bvr[2 * jj], bvr[2 * jj + 1]);
        }
        __syncthreads();
        buf ^= 1;
    }

    int ecb[4]; int ecn[4];
    #pragma unroll
    for (int nf = 0; nf < 4; nf++) {
        int col = n0 + ncol0 + nf * 8 + t4 * 2;
        int cb2 = col / NperB;
        ecb[nf] = cb2;
        ecn[nf] = col - cb2 * NperB;
    }
    #pragma unroll
    for (int mf = 0; mf < 4; mf++) {
        #pragma unroll
        for (int half = 0; half < 2; half++) {
            int o = o0 + mrow0 + mf * 16 + g + half * 8;
            float sc = gam[o] * rsqrtf(var[o] + BN_EPS);
            float mm = mu[o], bt = bet[o];
            #pragma unroll
            for (int nf = 0; nf < 4; nf++) {
                float y0 = (acc[mf][nf][half * 2 + 0] - mm) * sc + bt;
                float y1 = (acc[mf][nf][half * 2 + 1] - mm) * sc + bt;
                st_pair(Y + ((size_t)ecb[nf] * O + o) * NperB + ecn[nf],
                        hardswish(y0), hardswish(y1));
            }
        }
    }
}

// ---------------- fp16 tensor-core flash attention ---------------------------
// grid (512 bh, 2 qblocks), 256 threads / 8 warps, 16 queries per warp.
// K/V staged once per 128 queries; softmax via ex2.approx.f16x2 (half MUFU).
__global__ void __launch_bounds__(256)
attention_tc_kernel()
{
    const int bh = blockIdx.x;
    const int b = bh >> 3, h = bh & 7;
    const int qb = blockIdx.y;
    const int t = threadIdx.x;
    const int warp = t >> 5, lane = t & 31;
    const int g = lane >> 2, t4 = lane & 3;

    __shared__ uint32_t Ks[56 * 8];    // [m][d-pair perm], pitch 8 (exact)
    __shared__ uint32_t Vs[32 * 40];   // [d][m-pair perm], pitch 40

    const __half* kvb = g_kv + ((size_t)b * 384 + (size_t)h * 48) * 784;
    const __half* bsh = g_bias + (size_t)h * 196 * 784;

    // staging coordinates (256 threads)
    const int kRow = t >> 3, kp = t & 7;         // K: rows kRow, kRow+32
    const int kphys = pperm(kp);
    const __half* kp0 = kvb + (size_t)(2 * kp    ) * 784 + kRow;
    const __half* kp1 = kvb + (size_t)(2 * kp + 1) * 784 + kRow;
    const int vd = t >> 3, vl = t & 7;           // V: d 0..31, l = vl + 8*lp
    const __half* vrow = kvb + (size_t)(16 + vd) * 784;

    const int q0 = qb * 128 + warp * 16;
    const int qA = q0 + g, qB = q0 + g + 8;

    uint32_t qh[4];
    {
        const float QS = 0.25f * LOG2E;
        float qa0 = 0.f, qa1 = 0.f, qa8 = 0.f, qa9 = 0.f;
        float qb0 = 0.f, qb1 = 0.f, qb8 = 0.f, qb9 = 0.f;
        const __half* qbase = g_q + (size_t)b * 128 * 196 + (size_t)h * 16 * 196;
        if (qA < 196) {
            qa0 = __half2float(qbase[(2 * t4    ) * 196 + qA]) * QS;
            qa1 = __half2float(qbase[(2 * t4 + 1) * 196 + qA]) * QS;
            qa8 = __half2float(qbase[(2 * t4 + 8) * 196 + qA]) * QS;
            qa9 = __half2float(qbase[(2 * t4 + 9) * 196 + qA]) * QS;
        }
        if (qB < 196) {
            qb0 = __half2float(qbase[(2 * t4    ) * 196 + qB]) * QS;
            qb1 = __half2float(qbase[(2 * t4 + 1) * 196 + qB]) * QS;
            qb8 = __half2float(qbase[(2 * t4 + 8) * 196 + qB]) * QS;
            qb9 = __half2float(qbase[(2 * t4 + 9) * 196 + qB]) * QS;
        }
        qh[0] = pack_h2(qa0, qa1);
        qh[1] = pack_h2(qb0, qb1);
        qh[2] = pack_h2(qa8, qa9);
        qh[3] = pack_h2(qb8, qb9);
    }

    float oc[4][4];
    #pragma unroll
    for (int v = 0; v < 4; v++)
        #pragma unroll
        for (int e = 0; e < 4; e++) oc[v][e] = 0.f;
    float rm0 = -1e30f, rm1 = -1e30f, rl0 = 0.f, rl1 = 0.f;

    for (int m0 = 0; m0 < 784; m0 += 56) {
        // ---- stage K: each thread writes rows kRow and kRow+32 (if <56)
        Ks[kRow * 8 + kphys] = combine_h2(kp0[m0], kp1[m0]);
        if (kRow < 24)
            Ks[(kRow + 32) * 8 + kphys] = combine_h2(kp0[m0 + 32], kp1[m0 + 32]);
        // ---- stage V: pairs along m adjacent -> single 32-bit loads
        #pragma unroll
        for (int lp = 0; lp < 4; lp++) {
            int l = vl + 8 * lp;
            if (l < 28) {
                uint32_t pv = *reinterpret_cast<const uint32_t*>(vrow + m0 + 2 * l);
                int phys = ((l >> 3) << 3) + pperm(l & 7);
                Vs[vd * 40 + phys] = pv;
            }
        }
        __syncthreads();

        // ---- S = bias + Q K^T  (7 k16 mmas)
        float sc[7][4];
        #pragma unroll
        for (int j = 0; j < 7; j++) {
            int m = m0 + j * 8 + 2 * t4;
            if (qA < 196) {
                __half2 bv = *reinterpret_cast<const __half2*>(&bsh[(size_t)qA * 784 + m]);
                float2 bf = __half22float2(bv);
                sc[j][0] = bf.x; sc[j][1] = bf.y;
            } else { sc[j][0] = 0.f; sc[j][1] = 0.f; }
            if (qB < 196) {
                __half2 bv = *reinterpret_cast<const __half2*>(&bsh[(size_t)qB * 784 + m]);
                float2 bf = __half22float2(bv);
                sc[j][2] = bf.x; sc[j][3] = bf.y;
            } else { sc[j][2] = 0.f; sc[j][3] = 0.f; }
        }
        #pragma unroll
        for (int j = 0; j < 7; j++) {
            uint2 kk = *reinterpret_cast<const uint2*>(&Ks[(j * 8 + g) * 8 + 2 * t4]);
            mma_f16_k16(sc[j], qh, kk.x, kk.y);
        }

        // ---- online softmax (exp2 domain, fp16x2 exponentials)
        float mx0 = rm0, mx1 = rm1;
        #pragma unroll
        for (int j = 0; j < 7; j++) {
            mx0 = fmaxf(mx0, fmaxf(sc[j][0], sc[j][1]));
            mx1 = fmaxf(mx1, fmaxf(sc[j][2], sc[j][3]));
        }
        mx0 = fmaxf(mx0, __shfl_xor_sync(0xffffffffu, mx0, 1));
        mx0 = fmaxf(mx0, __shfl_xor_sync(0xffffffffu, mx0, 2));
        mx1 = fmaxf(mx1, __shfl_xor_sync(0xffffffffu, mx1, 1));
        mx1 = fmaxf(mx1, __shfl_xor_sync(0xffffffffu, mx1, 2));

        float a0 = exp2fast(rm0 - mx0), a1 = exp2fast(rm1 - mx1);
        rl0 *= a0; rl1 *= a1; rm0 = mx0; rm1 = mx1;
        #pragma unroll
        for (int v = 0; v < 4; v++) {
            oc[v][0] *= a0; oc[v][1] *= a0;
            oc[v][2] *= a1; oc[v][3] *= a1;
        }

        uint32_t ph[7][2];
        float s0 = 0.f, s1 = 0.f;
        #pragma unroll
        for (int j = 0; j < 7; j++) {
            uint32_t dA = pack_h2(sc[j][0] - mx0, sc[j][1] - mx0);
            uint32_t dB = pack_h2(sc[j][2] - mx1, sc[j][3] - mx1);
            uint32_t pA = h2exp2(dA);
            uint32_t pB = h2exp2(dB);
            ph[j][0] = pA;
            ph[j][1] = pB;
            float2 fA = __half22float2(*reinterpret_cast<__half2*>(&pA));
            float2 fB = __half22float2(*reinterpret_cast<__half2*>(&pB));
            s0 += fA.x + fA.y;
            s1 += fB.x + fB.y;
        }
        s0 += __shfl_xor_sync(0xffffffffu, s0, 1);
        s0 += __shfl_xor_sync(0xffffffffu, s0, 2);
        s1 += __shfl_xor_sync(0xffffffffu, s1, 1);
        s1 += __shfl_xor_sync(0xffffffffu, s1, 2);
        rl0 += s0; rl1 += s1;

        // ---- out += P @ V^T : 3 k16 + 1 k8 per d-group
        #pragma unroll
        for (int jj = 0; jj < 3; jj++) {
            uint32_t pa[4] = { ph[2*jj][0], ph[2*jj][1], ph[2*jj+1][0], ph[2*jj+1][1] };
            #pragma unroll
            for (int v = 0; v < 4; v++) {
                uint2 vv = *reinterpret_cast<const uint2*>(
                    &Vs[(v * 8 + g) * 40 + 8 * jj + 2 * t4]);
                mma_f16_k16(oc[v], pa, vv.x, vv.y);
            }
        }
        #pragma unroll
        for (int v = 0; v < 4; v++) {
            uint32_t vv = Vs[(v * 8 + g) * 40 + 24 + 2 * t4];
            mma_f16_k8(oc[v], ph[6][0], ph[6][1], vv);
        }
        __syncthreads();
    }

    // ---- normalize, hardswish, store (fp16)
    float inv0 = 1.f / rl0, inv1 = 1.f / rl1;
    #pragma unroll
    for (int v = 0; v < 4; v++) {
        #pragma unroll
        for (int e = 0; e < 2; e++) {
            int d = v * 8 + 2 * t4 + e;
            if (qA < 196)
                g_att[((size_t)b * 256 + h * 32 + d) * 196 + qA] =
                    __float2half(hardswish(oc[v][e] * inv0));
            if (qB < 196)
                g_att[((size_t)b * 256 + h * 32 + d) * 196 + qB] =
                    __float2half(hardswish(oc[v][2 + e] * inv1));
        }
    }
}

// ---------------- launch -----------------------------------------------------
extern "C" void kernel_launch(void* const* d_in, const int* in_sizes, int n_in,
                              void* d_out, int out_size)
{
    const float* x      = (const float*)d_in[0];
    const float* kv_w   = (const float*)d_in[1];
    const float* kv_g   = (const float*)d_in[2];
    const float* kv_b   = (const float*)d_in[3];
    const float* kv_m   = (const float*)d_in[4];
    const float* kv_v   = (const float*)d_in[5];
    const float* q_w    = (const float*)d_in[6];
    const float* q_g    = (const float*)d_in[7];
    const float* q_b    = (const float*)d_in[8];
    const float* q_m    = (const float*)d_in[9];
    const float* q_v    = (const float*)d_in[10];
    const float* proj_w = (const float*)d_in[11];
    const float* proj_g = (const float*)d_in[12];
    const float* proj_b = (const float*)d_in[13];
    const float* proj_m = (const float*)d_in[14];
    const float* proj_v = (const float*)d_in[15];
    const float* ab     = (const float*)d_in[16];
    const int*   idxs   = (const int*)  d_in[17];
    const int n_off = in_sizes[16] / 8;

    float* out = (float*)d_out;

    __half *p_kv, *p_q, *p_att;
    cudaGetSymbolAddress((void**)&p_kv,  g_kv);
    cudaGetSymbolAddress((void**)&p_q,   g_q);
    cudaGetSymbolAddress((void**)&p_att, g_att);

    // 1) bias table [h][q][m] (fp16, *log2e)
    bias_gather_kernel<<<dim3(196, 8), 784>>>(ab, idxs, n_off);

    // 2) kv: cols = 64*784 = 50176 = 392*128
    conv_bn_hsw_tc_kernel<false, float, __half><<<dim3(3, 392), 256>>>(
        x, 256 * 784, 784, kv_w, 256, kv_g, kv_b, kv_m, kv_v, p_kv, 384, 784);

    // 3) q: cols = 64*196 = 12544 = 98*128 (strided input gather)
    conv_bn_hsw_tc_kernel<true, float, __half><<<dim3(1, 98), 256>>>(
        x, 256 * 784, 784, q_w, 256, q_g, q_b, q_m, q_v, p_q, 128, 196);

    // 4) fp16 tensor-core flash attention -> g_att (with pre-proj hardswish)
    attention_tc_kernel<<<dim3(512, 2), 256>>>();

    // 5) proj: cols = 64*196 = 12544 = 98*128, fp16 in, fp32 out
    conv_bn_hsw_tc_kernel<false, __half, float><<<dim3(4, 98), 256>>>(
        p_att, 256 * 196, 196, proj_w, 256, proj_g, proj_b, proj_m, proj_v, out, 512, 196);
}

// round 12
// speedup vs baseline: 2.0539x; 1.0541x over previous
#include <cuda_runtime.h>
#include <cuda_fp16.h>
#include <math.h>
#include <stdint.h>

#define BN_EPS 1e-5f
#define LOG2E 1.4426950408889634f

// ---------------- scratch (static device buffers; no allocations) ----------
__device__ __half g_kv  [64u*384u*784u];  // kv conv output (fp16) [b][o][n]
__device__ __half g_q   [64u*128u*196u];  // q  conv output (fp16) [b][o][n]
__device__ __half g_bias[ 8u*196u*784u];  // bias*log2e (fp16) [h][q][m]
__device__ __half g_att [64u*256u*196u];  // hardswish(attn out) (fp16) [b][c][n]

__device__ __forceinline__ float hardswish(float x) {
    float t = fminf(fmaxf(x + 3.f, 0.f), 6.f);
    return x * t * (1.f / 6.f);
}

__device__ __forceinline__ uint32_t pack_h2(float lo, float hi) {
    uint32_t r;
    asm("cvt.rn.f16x2.f32 %0, %1, %2;" : "=r"(r) : "f"(hi), "f"(lo));
    return r;
}

__device__ __forceinline__ uint32_t combine_h2(__half lo, __half hi) {
    return (uint32_t)__half_as_ushort(lo) | ((uint32_t)__half_as_ushort(hi) << 16);
}

__device__ __forceinline__ float exp2fast(float x) {
    float y;
    asm("ex2.approx.f32 %0, %1;" : "=f"(y) : "f"(x));
    return y;
}

__device__ __forceinline__ uint32_t h2exp2(uint32_t x) {
    uint32_t y;
    asm("ex2.approx.f16x2 %0, %1;" : "=r"(y) : "r"(x));
    return y;
}

__device__ __forceinline__ void mma_f16_k16(float c[4], const uint32_t a[4],
                                            uint32_t b0, uint32_t b1) {
    asm volatile(
        "mma.sync.aligned.m16n8k16.row.col.f32.f16.f16.f32 "
        "{%0,%1,%2,%3}, {%4,%5,%6,%7}, {%8,%9}, {%0,%1,%2,%3};"
        : "+f"(c[0]), "+f"(c[1]), "+f"(c[2]), "+f"(c[3])
        : "r"(a[0]), "r"(a[1]), "r"(a[2]), "r"(a[3]), "r"(b0), "r"(b1));
}

__device__ __forceinline__ void mma_f16_k8(float c[4], uint32_t a0, uint32_t a1,
                                           uint32_t b0) {
    asm volatile(
        "mma.sync.aligned.m16n8k8.row.col.f32.f16.f16.f32 "
        "{%0,%1,%2,%3}, {%4,%5}, {%6}, {%0,%1,%2,%3};"
        : "+f"(c[0]), "+f"(c[1]), "+f"(c[2]), "+f"(c[3])
        : "r"(a0), "r"(a1), "r"(b0));
}

__device__ __forceinline__ float ld_in(const float* p)  { return *p; }
__device__ __forceinline__ float ld_in(const __half* p) { return __half2float(*p); }

__device__ __forceinline__ void st_pair(float* p, float y0, float y1) {
    *reinterpret_cast<float2*>(p) = make_float2(y0, y1);
}
__device__ __forceinline__ void st_pair(__half* p, float y0, float y1) {
    *reinterpret_cast<__half2*>(p) = __floats2half2_rn(y0, y1);
}

// pair permutation within groups of 8: phys = (p&3)*2 + (p>>2)
__device__ __forceinline__ int pperm(int p) { return ((p & 3) << 1) + (p >> 2); }

// ---------------- bias gather: g_bias[h][q][m] = half(ab[...] * log2e) -----
__global__ void bias_gather_kernel(const float* __restrict__ ab,
                                   const int*   __restrict__ idxs,
                                   int n_off)
{
    int q = blockIdx.x;
    int h = blockIdx.y;
    int m = threadIdx.x;
    int idx = idxs[q * 784 + m];
    g_bias[((size_t)h * 196 + q) * 784 + m] = __float2half(ab[h * n_off + idx] * LOG2E);
}

// ---------------- fp16 GEMM + BN + hardswish, batch-flattened N -------------
template<bool STRIDED, typename IN_T, typename OUT_T>
__global__ void __launch_bounds__(256, 2)
conv_bn_hsw_tc_kernel(const IN_T* __restrict__ X, int xbs, int ldx,
                      const float* __restrict__ W, int C,
                      const float* __restrict__ gam, const float* __restrict__ bet,
                      const float* __restrict__ mu,  const float* __restrict__ var,
                      OUT_T* __restrict__ Y, int O, int NperB)
{
    __shared__ uint32_t As[2][128][10];
    __shared__ uint32_t Bs[2][128][10];

    const int o0 = blockIdx.x * 128;
    const int n0 = blockIdx.y * 128;
    const int t  = threadIdx.x;

    const int warp = t >> 5;
    const int lane = t & 31;
    const int g    = lane >> 2;
    const int t4   = lane & 3;
    const int wm   = warp >> 2;
    const int wn   = warp & 3;
    const int mrow0 = wm * 64;
    const int ncol0 = wn * 32;

    const int arow0 = t >> 2, aseg = t & 3;
    const int aph0 = pperm(2 * aseg), aph1 = pperm(2 * aseg + 1);
    const int bcol = t & 127;
    const int bks  = t >> 7;
    const int colg = n0 + bcol;
    const int bb   = colg / NperB;
    int nn = colg - bb * NperB;
    if (STRIDED) nn = 2 * (nn / 14) * 28 + 2 * (nn % 14);
    const IN_T* bsrc = X + (size_t)bb * xbs + nn;

    float acc[4][4][4];
    #pragma unroll
    for (int i = 0; i < 4; i++)
        #pragma unroll
        for (int j = 0; j < 4; j++)
            #pragma unroll
            for (int e = 0; e < 4; e++) acc[i][j][e] = 0.f;

    float4 avr[2];
    float  bvr[8];

    #pragma unroll
    for (int r = 0; r < 2; r++)
        avr[r] = *reinterpret_cast<const float4*>(&W[(o0 + arow0 + r * 64) * C + aseg * 4]);
    #pragma unroll
    for (int j = 0; j < 8; j++)
        bvr[j] = ld_in(bsrc + (size_t)(bks * 8 + j) * ldx);

    #pragma unroll
    for (int r = 0; r < 2; r++) {
        int row = arow0 + r * 64;
        As[0][row][aph0] = pack_h2(avr[r].x, avr[r].y);
        As[0][row][aph1] = pack_h2(avr[r].z, avr[r].w);
    }
    #pragma unroll
    for (int jj = 0; jj < 4; jj++)
        Bs[0][bcol][pperm(bks * 4 + jj)] = pack_h2(bvr[2 * jj], bvr[2 * jj + 1]);
    __syncthreads();

    int buf = 0;
    const int nslab = C >> 4;
    for (int s = 0; s < nslab; s++) {
        const bool more = (s + 1 < nslab);
        const int c1 = (s + 1) << 4;
        if (more) {
            #pragma unroll
            for (int r = 0; r < 2; r++)
                avr[r] = *reinterpret_cast<const float4*>(
                    &W[(o0 + arow0 + r * 64) * C + c1 + aseg * 4]);
            #pragma unroll
            for (int j = 0; j < 8; j++)
                bvr[j] = ld_in(bsrc + (size_t)(c1 + bks * 8 + j) * ldx);
        }

        {
            uint32_t a[4][4];
            #pragma unroll
            for (int mf = 0; mf < 4; mf++) {
                int rb = mrow0 + mf * 16;
                uint2 lo = *reinterpret_cast<const uint2*>(&As[buf][rb + g    ][2 * t4]);
                uint2 hi = *reinterpret_cast<const uint2*>(&As[buf][rb + g + 8][2 * t4]);
                a[mf][0] = lo.x; a[mf][1] = hi.x; a[mf][2] = lo.y; a[mf][3] = hi.y;
            }
            uint2 bfr[4];
            #pragma unroll
            for (int nf = 0; nf < 4; nf++)
                bfr[nf] = *reinterpret_cast<const uint2*>(&Bs[buf][ncol0 + nf * 8 + g][2 * t4]);
            #pragma unroll
            for (int mf = 0; mf < 4; mf++)
                #pragma unroll
                for (int nf = 0; nf < 4; nf++)
                    mma_f16_k16(acc[mf][nf], a[mf], bfr[nf].x, bfr[nf].y);
        }

        if (more) {
            int nb = buf ^ 1;
            #pragma unroll
            for (int r = 0; r < 2; r++) {
                int row = arow0 + r * 64;
                As[nb][row][aph0] = pack_h2(avr[r].x, avr[r].y);
                As[nb][row][aph1] = pack_h2(avr[r].z, avr[r].w);
            }
            #pragma unroll
            for (int jj = 0; jj < 4; jj++)
                Bs[nb][bcol][pperm(bks * 4 + jj)] = pack_h2(bvr[2 * jj], bvr[2 * jj + 1]);
        }
        __syncthreads();
        buf ^= 1;
    }

    int ecb[4]; int ecn[4];
    #pragma unroll
    for (int nf = 0; nf < 4; nf++) {
        int col = n0 + ncol0 + nf * 8 + t4 * 2;
        int cb2 = col / NperB;
        ecb[nf] = cb2;
        ecn[nf] = col - cb2 * NperB;
    }
    #pragma unroll
    for (int mf = 0; mf < 4; mf++) {
        #pragma unroll
        for (int half = 0; half < 2; half++) {
            int o = o0 + mrow0 + mf * 16 + g + half * 8;
            float sc = gam[o] * rsqrtf(var[o] + BN_EPS);
            float mm = mu[o], bt = bet[o];
            #pragma unroll
            for (int nf = 0; nf < 4; nf++) {
                float y0 = (acc[mf][nf][half * 2 + 0] - mm) * sc + bt;
                float y1 = (acc[mf][nf][half * 2 + 1] - mm) * sc + bt;
                st_pair(Y + ((size_t)ecb[nf] * O + o) * NperB + ecn[nf],
                        hardswish(y0), hardswish(y1));
            }
        }
    }
}

// ---------------- fp16 tensor-core flash attention (double-buffered) --------
// grid (512 bh, 2 qblocks), 256 threads / 8 warps, 16 queries per warp.
// K/V staging ping-pongs: LDG i+1 | compute i | STS i+1 | one sync per chunk.
__global__ void __launch_bounds__(256)
attention_tc_kernel()
{
    const int bh = blockIdx.x;
    const int b = bh >> 3, h = bh & 7;
    const int qb = blockIdx.y;
    const int t = threadIdx.x;
    const int warp = t >> 5, lane = t & 31;
    const int g = lane >> 2, t4 = lane & 3;

    __shared__ uint32_t Ks[2][56 * 8];    // [m][d-pair perm], pitch 8
    __shared__ uint32_t Vs[2][32 * 40];   // [d][m-pair perm], pitch 40

    const __half* kvb = g_kv + ((size_t)b * 384 + (size_t)h * 48) * 784;
    const __half* bsh = g_bias + (size_t)h * 196 * 784;

    // staging coordinates (256 threads)
    const int kRow = t >> 3, kp = t & 7;         // K: rows kRow, kRow+32
    const int kphys = pperm(kp);
    const __half* kp0 = kvb + (size_t)(2 * kp    ) * 784 + kRow;
    const __half* kp1 = kvb + (size_t)(2 * kp + 1) * 784 + kRow;
    const int vd = t >> 3, vl = t & 7;           // V: d 0..31, l = vl + 8*lp
    const __half* vrow = kvb + (size_t)(16 + vd) * 784;
    const bool kHi = (kRow < 24);

    const int q0 = qb * 128 + warp * 16;
    const int qA = q0 + g, qB = q0 + g + 8;

    uint32_t qh[4];
    {
        const float QS = 0.25f * LOG2E;
        float qa0 = 0.f, qa1 = 0.f, qa8 = 0.f, qa9 = 0.f;
        float qb0 = 0.f, qb1 = 0.f, qb8 = 0.f, qb9 = 0.f;
        const __half* qbase = g_q + (size_t)b * 128 * 196 + (size_t)h * 16 * 196;
        if (qA < 196) {
            qa0 = __half2float(qbase[(2 * t4    ) * 196 + qA]) * QS;
            qa1 = __half2float(qbase[(2 * t4 + 1) * 196 + qA]) * QS;
            qa8 = __half2float(qbase[(2 * t4 + 8) * 196 + qA]) * QS;
            qa9 = __half2float(qbase[(2 * t4 + 9) * 196 + qA]) * QS;
        }
        if (qB < 196) {
            qb0 = __half2float(qbase[(2 * t4    ) * 196 + qB]) * QS;
            qb1 = __half2float(qbase[(2 * t4 + 1) * 196 + qB]) * QS;
            qb8 = __half2float(qbase[(2 * t4 + 8) * 196 + qB]) * QS;
            qb9 = __half2float(qbase[(2 * t4 + 9) * 196 + qB]) * QS;
        }
        qh[0] = pack_h2(qa0, qa1);
        qh[1] = pack_h2(qb0, qb1);
        qh[2] = pack_h2(qa8, qa9);
        qh[3] = pack_h2(qb8, qb9);
    }

    float oc[4][4];
    #pragma unroll
    for (int v = 0; v < 4; v++)
        #pragma unroll
        for (int e = 0; e < 4; e++) oc[v][e] = 0.f;
    float rm0 = -1e30f, rm1 = -1e30f, rl0 = 0.f, rl1 = 0.f;

    // ---- prologue: load + store chunk 0
    __half ka0 = kp0[0], ka1 = kp1[0];
    __half kb0 = __float2half(0.f), kb1 = __float2half(0.f);
    if (kHi) { kb0 = kp0[32]; kb1 = kp1[32]; }
    uint32_t vreg[4];
    #pragma unroll
    for (int lp = 0; lp < 4; lp++) {
        int l = vl + 8 * lp;
        vreg[lp] = (l < 28) ? *reinterpret_cast<const uint32_t*>(vrow + 2 * l) : 0u;
    }
    Ks[0][kRow * 8 + kphys] = combine_h2(ka0, ka1);
    if (kHi) Ks[0][(kRow + 32) * 8 + kphys] = combine_h2(kb0, kb1);
    #pragma unroll
    for (int lp = 0; lp < 4; lp++) {
        int l = vl + 8 * lp;
        if (l < 28) Vs[0][vd * 40 + ((l >> 3) << 3) + pperm(l & 7)] = vreg[lp];
    }
    __syncthreads();

    int buf = 0;
    for (int c = 0; c < 14; c++) {
        const int m0 = c * 56;
        const bool more = (c + 1 < 14);
        const int m1 = m0 + 56;

        // ---- prefetch chunk c+1 (LDGs issued before compute)
        if (more) {
            ka0 = kp0[m1]; ka1 = kp1[m1];
            if (kHi) { kb0 = kp0[m1 + 32]; kb1 = kp1[m1 + 32]; }
            #pragma unroll
            for (int lp = 0; lp < 4; lp++) {
                int l = vl + 8 * lp;
                if (l < 28)
                    vreg[lp] = *reinterpret_cast<const uint32_t*>(vrow + m1 + 2 * l);
            }
        }

        // ---- S = bias + Q K^T  (7 k16 mmas)
        float sc[7][4];
        #pragma unroll
        for (int j = 0; j < 7; j++) {
            int m = m0 + j * 8 + 2 * t4;
            if (qA < 196) {
                __half2 bv = *reinterpret_cast<const __half2*>(&bsh[(size_t)qA * 784 + m]);
                float2 bf = __half22float2(bv);
                sc[j][0] = bf.x; sc[j][1] = bf.y;
            } else { sc[j][0] = 0.f; sc[j][1] = 0.f; }
            if (qB < 196) {
                __half2 bv = *reinterpret_cast<const __half2*>(&bsh[(size_t)qB * 784 + m]);
                float2 bf = __half22float2(bv);
                sc[j][2] = bf.x; sc[j][3] = bf.y;
            } else { sc[j][2] = 0.f; sc[j][3] = 0.f; }
        }
        #pragma unroll
        for (int j = 0; j < 7; j++) {
            uint2 kk = *reinterpret_cast<const uint2*>(&Ks[buf][(j * 8 + g) * 8 + 2 * t4]);
            mma_f16_k16(sc[j], qh, kk.x, kk.y);
        }

        // ---- online softmax (exp2 domain, fp16x2 exponentials)
        float mx0 = rm0, mx1 = rm1;
        #pragma unroll
        for (int j = 0; j < 7; j++) {
            mx0 = fmaxf(mx0, fmaxf(sc[j][0], sc[j][1]));
            mx1 = fmaxf(mx1, fmaxf(sc[j][2], sc[j][3]));
        }
        mx0 = fmaxf(mx0, __shfl_xor_sync(0xffffffffu, mx0, 1));
        mx0 = fmaxf(mx0, __shfl_xor_sync(0xffffffffu, mx0, 2));
        mx1 = fmaxf(mx1, __shfl_xor_sync(0xffffffffu, mx1, 1));
        mx1 = fmaxf(mx1, __shfl_xor_sync(0xffffffffu, mx1, 2));

        float a0 = exp2fast(rm0 - mx0), a1 = exp2fast(rm1 - mx1);
        rl0 *= a0; rl1 *= a1; rm0 = mx0; rm1 = mx1;
        #pragma unroll
        for (int v = 0; v < 4; v++) {
            oc[v][0] *= a0; oc[v][1] *= a0;
            oc[v][2] *= a1; oc[v][3] *= a1;
        }

        uint32_t ph[7][2];
        float s0 = 0.f, s1 = 0.f;
        #pragma unroll
        for (int j = 0; j < 7; j++) {
            uint32_t dA = pack_h2(sc[j][0] - mx0, sc[j][1] - mx0);
            uint32_t dB = pack_h2(sc[j][2] - mx1, sc[j][3] - mx1);
            uint32_t pA = h2exp2(dA);
            uint32_t pB = h2exp2(dB);
            ph[j][0] = pA;
            ph[j][1] = pB;
            float2 fA = __half22float2(*reinterpret_cast<__half2*>(&pA));
            float2 fB = __half22float2(*reinterpret_cast<__half2*>(&pB));
            s0 += fA.x + fA.y;
            s1 += fB.x + fB.y;
        }
        s0 += __shfl_xor_sync(0xffffffffu, s0, 1);
        s0 += __shfl_xor_sync(0xffffffffu, s0, 2);
        s1 += __shfl_xor_sync(0xffffffffu, s1, 1);
        s1 += __shfl_xor_sync(0xffffffffu, s1, 2);
        rl0 += s0; rl1 += s1;

        // ---- out += P @ V^T : 3 k16 + 1 k8 per d-group
        #pragma unroll
        for (int jj = 0; jj < 3; jj++) {
            uint32_t pa[4] = { ph[2*jj][0], ph[2*jj][1], ph[2*jj+1][0], ph[2*jj+1][1] };
            #pragma unroll
            for (int v = 0; v < 4; v++) {
                uint2 vv = *reinterpret_cast<const uint2*>(
                    &Vs[buf][(v * 8 + g) * 40 + 8 * jj + 2 * t4]);
                mma_f16_k16(oc[v], pa, vv.x, vv.y);
            }
        }
        #pragma unroll
        for (int v = 0; v < 4; v++) {
            uint32_t vv = Vs[buf][(v * 8 + g) * 40 + 24 + 2 * t4];
            mma_f16_k8(oc[v], ph[6][0], ph[6][1], vv);
        }

        // ---- store chunk c+1 into the alternate buffer, single sync
        if (more) {
            int nb = buf ^ 1;
            Ks[nb][kRow * 8 + kphys] = combine_h2(ka0, ka1);
            if (kHi) Ks[nb][(kRow + 32) * 8 + kphys] = combine_h2(kb0, kb1);
            #pragma unroll
            for (int lp = 0; lp < 4; lp++) {
                int l = vl + 8 * lp;
                if (l < 28) Vs[nb][vd * 40 + ((l >> 3) << 3) + pperm(l & 7)] = vreg[lp];
            }
            __syncthreads();
        }
        buf ^= 1;
    }

    // ---- normalize, hardswish, store (fp16)
    float inv0 = 1.f / rl0, inv1 = 1.f / rl1;
    #pragma unroll
    for (int v = 0; v < 4; v++) {
        #pragma unroll
        for (int e = 0; e < 2; e++) {
            int d = v * 8 + 2 * t4 + e;
            if (qA < 196)
                g_att[((size_t)b * 256 + h * 32 + d) * 196 + qA] =
                    __float2half(hardswish(oc[v][e] * inv0));
            if (qB < 196)
                g_att[((size_t)b * 256 + h * 32 + d) * 196 + qB] =
                    __float2half(hardswish(oc[v][2 + e] * inv1));
        }
    }
}

// ---------------- launch -----------------------------------------------------
extern "C" void kernel_launch(void* const* d_in, const int* in_sizes, int n_in,
                              void* d_out, int out_size)
{
    const float* x      = (const float*)d_in[0];
    const float* kv_w   = (const float*)d_in[1];
    const float* kv_g   = (const float*)d_in[2];
    const float* kv_b   = (const float*)d_in[3];
    const float* kv_m   = (const float*)d_in[4];
    const float* kv_v   = (const float*)d_in[5];
    const float* q_w    = (const float*)d_in[6];
    const float* q_g    = (const float*)d_in[7];
    const float* q_b    = (const float*)d_in[8];
    const float* q_m    = (const float*)d_in[9];
    const float* q_v    = (const float*)d_in[10];
    const float* proj_w = (const float*)d_in[11];
    const float* proj_g = (const float*)d_in[12];
    const float* proj_b = (const float*)d_in[13];
    const float* proj_m = (const float*)d_in[14];
    const float* proj_v = (const float*)d_in[15];
    const float* ab     = (const float*)d_in[16];
    const int*   idxs   = (const int*)  d_in[17];
    const int n_off = in_sizes[16] / 8;

    float* out = (float*)d_out;

    __half *p_kv, *p_q, *p_att;
    cudaGetSymbolAddress((void**)&p_kv,  g_kv);
    cudaGetSymbolAddress((void**)&p_q,   g_q);
    cudaGetSymbolAddress((void**)&p_att, g_att);

    // 1) bias table [h][q][m] (fp16, *log2e)
    bias_gather_kernel<<<dim3(196, 8), 784>>>(ab, idxs, n_off);

    // 2) kv: cols = 64*784 = 50176 = 392*128
    conv_bn_hsw_tc_kernel<false, float, __half><<<dim3(3, 392), 256>>>(
        x, 256 * 784, 784, kv_w, 256, kv_g, kv_b, kv_m, kv_v, p_kv, 384, 784);

    // 3) q: cols = 64*196 = 12544 = 98*128 (strided input gather)
    conv_bn_hsw_tc_kernel<true, float, __half><<<dim3(1, 98), 256>>>(
        x, 256 * 784, 784, q_w, 256, q_g, q_b, q_m, q_v, p_q, 128, 196);

    // 4) fp16 tensor-core flash attention -> g_att (with pre-proj hardswish)
    attention_tc_kernel<<<dim3(512, 2), 256>>>();

    // 5) proj: cols = 64*196 = 12544 = 98*128, fp16 in, fp32 out
    conv_bn_hsw_tc_kernel<false, __half, float><<<dim3(4, 98), 256>>>(
        p_att, 256 * 196, 196, proj_w, 256, proj_g, proj_b, proj_m, proj_v, out, 512, 196);
}

// round 14
// speedup vs baseline: 2.1089x; 1.0268x over previous
#include <cuda_runtime.h>
#include <cuda_fp16.h>
#include <math.h>
#include <stdint.h>

#define BN_EPS 1e-5f
#define LOG2E 1.4426950408889634f

// ---------------- scratch (static device buffers; no allocations) ----------
__device__ __half g_kv  [64u*384u*784u];  // kv conv output (fp16) [b][o][n]
__device__ __half g_q   [64u*128u*196u];  // q  conv output (fp16) [b][o][n]
__device__ __half g_bias[ 8u*196u*784u];  // bias*log2e (fp16) [h][q][m]
__device__ __half g_att [64u*256u*196u];  // hardswish(attn out) (fp16) [b][c][n]

__device__ __forceinline__ float hardswish(float x) {
    float t = fminf(fmaxf(x + 3.f, 0.f), 6.f);
    return x * t * (1.f / 6.f);
}

__device__ __forceinline__ uint32_t pack_h2(float lo, float hi) {
    uint32_t r;
    asm("cvt.rn.f16x2.f32 %0, %1, %2;" : "=r"(r) : "f"(hi), "f"(lo));
    return r;
}

__device__ __forceinline__ uint32_t combine_h2(__half lo, __half hi) {
    return (uint32_t)__half_as_ushort(lo) | ((uint32_t)__half_as_ushort(hi) << 16);
}

__device__ __forceinline__ float exp2fast(float x) {
    float y;
    asm("ex2.approx.f32 %0, %1;" : "=f"(y) : "f"(x));
    return y;
}

__device__ __forceinline__ uint32_t h2exp2(uint32_t x) {
    uint32_t y;
    asm("ex2.approx.f16x2 %0, %1;" : "=r"(y) : "r"(x));
    return y;
}

__device__ __forceinline__ void mma_f16_k16(float c[4], const uint32_t a[4],
                                            uint32_t b0, uint32_t b1) {
    asm volatile(
        "mma.sync.aligned.m16n8k16.row.col.f32.f16.f16.f32 "
        "{%0,%1,%2,%3}, {%4,%5,%6,%7}, {%8,%9}, {%0,%1,%2,%3};"
        : "+f"(c[0]), "+f"(c[1]), "+f"(c[2]), "+f"(c[3])
        : "r"(a[0]), "r"(a[1]), "r"(a[2]), "r"(a[3]), "r"(b0), "r"(b1));
}

__device__ __forceinline__ void mma_f16_k8(float c[4], uint32_t a0, uint32_t a1,
                                           uint32_t b0) {
    asm volatile(
        "mma.sync.aligned.m16n8k8.row.col.f32.f16.f16.f32 "
        "{%0,%1,%2,%3}, {%4,%5}, {%6}, {%0,%1,%2,%3};"
        : "+f"(c[0]), "+f"(c[1]), "+f"(c[2]), "+f"(c[3])
        : "r"(a0), "r"(a1), "r"(b0));
}

__device__ __forceinline__ float ld_in(const float* p)  { return *p; }
__device__ __forceinline__ float ld_in(const __half* p) { return __half2float(*p); }

__device__ __forceinline__ void st_pair(float* p, float y0, float y1) {
    *reinterpret_cast<float2*>(p) = make_float2(y0, y1);
}
__device__ __forceinline__ void st_pair(__half* p, float y0, float y1) {
    *reinterpret_cast<__half2*>(p) = __floats2half2_rn(y0, y1);
}

// pair permutation within groups of 8: phys = (p&3)*2 + (p>>2)
__device__ __forceinline__ int pperm(int p) { return ((p & 3) << 1) + (p >> 2); }

// ---------------- bias gather (half2 stores): g_bias[h][q][m] ---------------
__global__ void bias_gather_kernel(const float* __restrict__ ab,
                                   const int*   __restrict__ idxs,
                                   int n_off)
{
    int q = blockIdx.x;
    int h = blockIdx.y;
    int m = threadIdx.x * 2;   // 392 threads, 2 m each
    int i0 = idxs[q * 784 + m];
    int i1 = idxs[q * 784 + m + 1];
    __half2 v = __floats2half2_rn(ab[h * n_off + i0] * LOG2E,
                                  ab[h * n_off + i1] * LOG2E);
    *reinterpret_cast<__half2*>(&g_bias[((size_t)h * 196 + q) * 784 + m]) = v;
}

// ---------------- fp16 GEMM + BN + hardswish, batch-flattened N -------------
template<bool STRIDED, typename IN_T, typename OUT_T>
__global__ void __launch_bounds__(256, 2)
conv_bn_hsw_tc_kernel(const IN_T* __restrict__ X, int xbs, int ldx,
                      const float* __restrict__ W, int C,
                      const float* __restrict__ gam, const float* __restrict__ bet,
                      const float* __restrict__ mu,  const float* __restrict__ var,
                      OUT_T* __restrict__ Y, int O, int NperB)
{
    __shared__ uint32_t As[2][128][10];
    __shared__ uint32_t Bs[2][128][10];

    const int o0 = blockIdx.x * 128;
    const int n0 = blockIdx.y * 128;
    const int t  = threadIdx.x;

    const int warp = t >> 5;
    const int lane = t & 31;
    const int g    = lane >> 2;
    const int t4   = lane & 3;
    const int wm   = warp >> 2;
    const int wn   = warp & 3;
    const int mrow0 = wm * 64;
    const int ncol0 = wn * 32;

    const int arow0 = t >> 2, aseg = t & 3;
    const int aph0 = pperm(2 * aseg), aph1 = pperm(2 * aseg + 1);
    const int bcol = t & 127;
    const int bks  = t >> 7;
    const int colg = n0 + bcol;
    const int bb   = colg / NperB;
    int nn = colg - bb * NperB;
    if (STRIDED) nn = 2 * (nn / 14) * 28 + 2 * (nn % 14);
    const IN_T* bsrc = X + (size_t)bb * xbs + nn;

    float acc[4][4][4];
    #pragma unroll
    for (int i = 0; i < 4; i++)
        #pragma unroll
        for (int j = 0; j < 4; j++)
            #pragma unroll
            for (int e = 0; e < 4; e++) acc[i][j][e] = 0.f;

    float4 avr[2];
    float  bvr[8];

    #pragma unroll
    for (int r = 0; r < 2; r++)
        avr[r] = *reinterpret_cast<const float4*>(&W[(o0 + arow0 + r * 64) * C + aseg * 4]);
    #pragma unroll
    for (int j = 0; j < 8; j++)
        bvr[j] = ld_in(bsrc + (size_t)(bks * 8 + j) * ldx);

    #pragma unroll
    for (int r = 0; r < 2; r++) {
        int row = arow0 + r * 64;
        As[0][row][aph0] = pack_h2(avr[r].x, avr[r].y);
        As[0][row][aph1] = pack_h2(avr[r].z, avr[r].w);
    }
    #pragma unroll
    for (int jj = 0; jj < 4; jj++)
        Bs[0][bcol][pperm(bks * 4 + jj)] = pack_h2(bvr[2 * jj], bvr[2 * jj + 1]);
    __syncthreads();

    int buf = 0;
    const int nslab = C >> 4;
    for (int s = 0; s < nslab; s++) {
        const bool more = (s + 1 < nslab);
        const int c1 = (s + 1) << 4;
        if (more) {
            #pragma unroll
            for (int r = 0; r < 2; r++)
                avr[r] = *reinterpret_cast<const float4*>(
                    &W[(o0 + arow0 + r * 64) * C + c1 + aseg * 4]);
            #pragma unroll
            for (int j = 0; j < 8; j++)
                bvr[j] = ld_in(bsrc + (size_t)(c1 + bks * 8 + j) * ldx);
        }

        {
            uint32_t a[4][4];
            #pragma unroll
            for (int mf = 0; mf < 4; mf++) {
                int rb = mrow0 + mf * 16;
                uint2 lo = *reinterpret_cast<const uint2*>(&As[buf][rb + g    ][2 * t4]);
                uint2 hi = *reinterpret_cast<const uint2*>(&As[buf][rb + g + 8][2 * t4]);
                a[mf][0] = lo.x; a[mf][1] = hi.x; a[mf][2] = lo.y; a[mf][3] = hi.y;
            }
            uint2 bfr[4];
            #pragma unroll
            for (int nf = 0; nf < 4; nf++)
                bfr[nf] = *reinterpret_cast<const uint2*>(&Bs[buf][ncol0 + nf * 8 + g][2 * t4]);
            #pragma unroll
            for (int mf = 0; mf < 4; mf++)
                #pragma unroll
                for (int nf = 0; nf < 4; nf++)
                    mma_f16_k16(acc[mf][nf], a[mf], bfr[nf].x, bfr[nf].y);
        }

        if (more) {
            int nb = buf ^ 1;
            #pragma unroll
            for (int r = 0; r < 2; r++) {
                int row = arow0 + r * 64;
                As[nb][row][aph0] = pack_h2(avr[r].x, avr[r].y);
                As[nb][row][aph1] = pack_h2(avr[r].z, avr[r].w);
            }
            #pragma unroll
            for (int jj = 0; jj < 4; jj++)
                Bs[nb][bcol][pperm(bks * 4 + jj)] = pack_h2(bvr[2 * jj], bvr[2 * jj + 1]);
        }
        __syncthreads();
        buf ^= 1;
    }

    int ecb[4]; int ecn[4];
    #pragma unroll
    for (int nf = 0; nf < 4; nf++) {
        int col = n0 + ncol0 + nf * 8 + t4 * 2;
        int cb2 = col / NperB;
        ecb[nf] = cb2;
        ecn[nf] = col - cb2 * NperB;
    }
    #pragma unroll
    for (int mf = 0; mf < 4; mf++) {
        #pragma unroll
        for (int half = 0; half < 2; half++) {
            int o = o0 + mrow0 + mf * 16 + g + half * 8;
            float sc = gam[o] * rsqrtf(var[o] + BN_EPS);
            float mm = mu[o], bt = bet[o];
            #pragma unroll
            for (int nf = 0; nf < 4; nf++) {
                float y0 = (acc[mf][nf][half * 2 + 0] - mm) * sc + bt;
                float y1 = (acc[mf][nf][half * 2 + 1] - mm) * sc + bt;
                st_pair(Y + ((size_t)ecb[nf] * O + o) * NperB + ecn[nf],
                        hardswish(y0), hardswish(y1));
            }
        }
    }
}

// ---------------- fp16 tensor-core flash attention (double-buffered) --------
// grid (512 bh, 2 qblocks), 256 threads / 8 warps, 16 queries per warp.
__global__ void __launch_bounds__(256)
attention_tc_kernel()
{
    const int bh = blockIdx.x;
    const int b = bh >> 3, h = bh & 7;
    const int qb = blockIdx.y;
    const int t = threadIdx.x;
    const int warp = t >> 5, lane = t & 31;
    const int g = lane >> 2, t4 = lane & 3;

    __shared__ uint32_t Ks[2][56 * 8];    // [m][d-pair perm], pitch 8
    __shared__ uint32_t Vs[2][32 * 40];   // [d][m-pair perm], pitch 40

    const __half* kvb = g_kv + ((size_t)b * 384 + (size_t)h * 48) * 784;
    const __half* bsh = g_bias + (size_t)h * 196 * 784;

    const int kRow = t >> 3, kp = t & 7;
    const int kphys = pperm(kp);
    const __half* kp0 = kvb + (size_t)(2 * kp    ) * 784 + kRow;
    const __half* kp1 = kvb + (size_t)(2 * kp + 1) * 784 + kRow;
    const int vd = t >> 3, vl = t & 7;
    const __half* vrow = kvb + (size_t)(16 + vd) * 784;
    const bool kHi = (kRow < 24);

    const int q0 = qb * 128 + warp * 16;
    const int qA = q0 + g, qB = q0 + g + 8;

    uint32_t qh[4];
    {
        const float QS = 0.25f * LOG2E;
        float qa0 = 0.f, qa1 = 0.f, qa8 = 0.f, qa9 = 0.f;
        float qb0 = 0.f, qb1 = 0.f, qb8 = 0.f, qb9 = 0.f;
        const __half* qbase = g_q + (size_t)b * 128 * 196 + (size_t)h * 16 * 196;
        if (qA < 196) {
            qa0 = __half2float(qbase[(2 * t4    ) * 196 + qA]) * QS;
            qa1 = __half2float(qbase[(2 * t4 + 1) * 196 + qA]) * QS;
            qa8 = __half2float(qbase[(2 * t4 + 8) * 196 + qA]) * QS;
            qa9 = __half2float(qbase[(2 * t4 + 9) * 196 + qA]) * QS;
        }
        if (qB < 196) {
            qb0 = __half2float(qbase[(2 * t4    ) * 196 + qB]) * QS;
            qb1 = __half2float(qbase[(2 * t4 + 1) * 196 + qB]) * QS;
            qb8 = __half2float(qbase[(2 * t4 + 8) * 196 + qB]) * QS;
            qb9 = __half2float(qbase[(2 * t4 + 9) * 196 + qB]) * QS;
        }
        qh[0] = pack_h2(qa0, qa1);
        qh[1] = pack_h2(qb0, qb1);
        qh[2] = pack_h2(qa8, qa9);
        qh[3] = pack_h2(qb8, qb9);
    }

    float oc[4][4];
    #pragma unroll
    for (int v = 0; v < 4; v++)
        #pragma unroll
        for (int e = 0; e < 4; e++) oc[v][e] = 0.f;
    float rm0 = -1e30f, rm1 = -1e30f, rl0 = 0.f, rl1 = 0.f;

    __half ka0 = kp0[0], ka1 = kp1[0];
    __half kb0 = __float2half(0.f), kb1 = __float2half(0.f);
    if (kHi) { kb0 = kp0[32]; kb1 = kp1[32]; }
    uint32_t vreg[4];
    #pragma unroll
    for (int lp = 0; lp < 4; lp++) {
        int l = vl + 8 * lp;
        vreg[lp] = (l < 28) ? *reinterpret_cast<const uint32_t*>(vrow + 2 * l) : 0u;
    }
    Ks[0][kRow * 8 + kphys] = combine_h2(ka0, ka1);
    if (kHi) Ks[0][(kRow + 32) * 8 + kphys] = combine_h2(kb0, kb1);
    #pragma unroll
    for (int lp = 0; lp < 4; lp++) {
        int l = vl + 8 * lp;
        if (l < 28) Vs[0][vd * 40 + ((l >> 3) << 3) + pperm(l & 7)] = vreg[lp];
    }
    __syncthreads();

    int buf = 0;
    for (int c = 0; c < 14; c++) {
        const int m0 = c * 56;
        const bool more = (c + 1 < 14);
        const int m1 = m0 + 56;

        if (more) {
            ka0 = kp0[m1]; ka1 = kp1[m1];
            if (kHi) { kb0 = kp0[m1 + 32]; kb1 = kp1[m1 + 32]; }
            #pragma unroll
            for (int lp = 0; lp < 4; lp++) {
                int l = vl + 8 * lp;
                if (l < 28)
                    vreg[lp] = *reinterpret_cast<const uint32_t*>(vrow + m1 + 2 * l);
            }
        }

        float sc[7][4];
        #pragma unroll
        for (int j = 0; j < 7; j++) {
            int m = m0 + j * 8 + 2 * t4;
            if (qA < 196) {
                __half2 bv = *reinterpret_cast<const __half2*>(&bsh[(size_t)qA * 784 + m]);
                float2 bf = __half22float2(bv);
                sc[j][0] = bf.x; sc[j][1] = bf.y;
            } else { sc[j][0] = 0.f; sc[j][1] = 0.f; }
            if (qB < 196) {
                __half2 bv = *reinterpret_cast<const __half2*>(&bsh[(size_t)qB * 784 + m]);
                float2 bf = __half22float2(bv);
                sc[j][2] = bf.x; sc[j][3] = bf.y;
            } else { sc[j][2] = 0.f; sc[j][3] = 0.f; }
        }
        #pragma unroll
        for (int j = 0; j < 7; j++) {
            uint2 kk = *reinterpret_cast<const uint2*>(&Ks[buf][(j * 8 + g) * 8 + 2 * t4]);
            mma_f16_k16(sc[j], qh, kk.x, kk.y);
        }

        float mx0 = rm0, mx1 = rm1;
        #pragma unroll
        for (int j = 0; j < 7; j++) {
            mx0 = fmaxf(mx0, fmaxf(sc[j][0], sc[j][1]));
            mx1 = fmaxf(mx1, fmaxf(sc[j][2], sc[j][3]));
        }
        mx0 = fmaxf(mx0, __shfl_xor_sync(0xffffffffu, mx0, 1));
        mx0 = fmaxf(mx0, __shfl_xor_sync(0xffffffffu, mx0, 2));
        mx1 = fmaxf(mx1, __shfl_xor_sync(0xffffffffu, mx1, 1));
        mx1 = fmaxf(mx1, __shfl_xor_sync(0xffffffffu, mx1, 2));

        float a0 = exp2fast(rm0 - mx0), a1 = exp2fast(rm1 - mx1);
        rl0 *= a0; rl1 *= a1; rm0 = mx0; rm1 = mx1;
        #pragma unroll
        for (int v = 0; v < 4; v++) {
            oc[v][0] *= a0; oc[v][1] *= a0;
            oc[v][2] *= a1; oc[v][3] *= a1;
        }

        uint32_t ph[7][2];
        float s0 = 0.f, s1 = 0.f;
        #pragma unroll
        for (int j = 0; j < 7; j++) {
            uint32_t dA = pack_h2(sc[j][0] - mx0, sc[j][1] - mx0);
            uint32_t dB = pack_h2(sc[j][2] - mx1, sc[j][3] - mx1);
            uint32_t pA = h2exp2(dA);
            uint32_t pB = h2exp2(dB);
            ph[j][0] = pA;
            ph[j][1] = pB;
            float2 fA = __half22float2(*reinterpret_cast<__half2*>(&pA));
            float2 fB = __half22float2(*reinterpret_cast<__half2*>(&pB));
            s0 += fA.x + fA.y;
            s1 += fB.x + fB.y;
        }
        s0 += __shfl_xor_sync(0xffffffffu, s0, 1);
        s0 += __shfl_xor_sync(0xffffffffu, s0, 2);
        s1 += __shfl_xor_sync(0xffffffffu, s1, 1);
        s1 += __shfl_xor_sync(0xffffffffu, s1, 2);
        rl0 += s0; rl1 += s1;

        #pragma unroll
        for (int jj = 0; jj < 3; jj++) {
            uint32_t pa[4] = { ph[2*jj][0], ph[2*jj][1], ph[2*jj+1][0], ph[2*jj+1][1] };
            #pragma unroll
            for (int v = 0; v < 4; v++) {
                uint2 vv = *reinterpret_cast<const uint2*>(
                    &Vs[buf][(v * 8 + g) * 40 + 8 * jj + 2 * t4]);
                mma_f16_k16(oc[v], pa, vv.x, vv.y);
            }
        }
        #pragma unroll
        for (int v = 0; v < 4; v++) {
            uint32_t vv = Vs[buf][(v * 8 + g) * 40 + 24 + 2 * t4];
            mma_f16_k8(oc[v], ph[6][0], ph[6][1], vv);
        }

        if (more) {
            int nb = buf ^ 1;
            Ks[nb][kRow * 8 + kphys] = combine_h2(ka0, ka1);
            if (kHi) Ks[nb][(kRow + 32) * 8 + kphys] = combine_h2(kb0, kb1);
            #pragma unroll
            for (int lp = 0; lp < 4; lp++) {
                int l = vl + 8 * lp;
                if (l < 28) Vs[nb][vd * 40 + ((l >> 3) << 3) + pperm(l & 7)] = vreg[lp];
            }
            __syncthreads();
        }
        buf ^= 1;
    }

    float inv0 = 1.f / rl0, inv1 = 1.f / rl1;
    #pragma unroll
    for (int v = 0; v < 4; v++) {
        #pragma unroll
        for (int e = 0; e < 2; e++) {
            int d = v * 8 + 2 * t4 + e;
            if (qA < 196)
                g_att[((size_t)b * 256 + h * 32 + d) * 196 + qA] =
                    __float2half(hardswish(oc[v][e] * inv0));
            if (qB < 196)
                g_att[((size_t)b * 256 + h * 32 + d) * 196 + qB] =
                    __float2half(hardswish(oc[v][2 + e] * inv1));
        }
    }
}

// ---------------- launch -----------------------------------------------------
extern "C" void kernel_launch(void* const* d_in, const int* in_sizes, int n_in,
                              void* d_out, int out_size)
{
    const float* x      = (const float*)d_in[0];
    const float* kv_w   = (const float*)d_in[1];
    const float* kv_g   = (const float*)d_in[2];
    const float* kv_b   = (const float*)d_in[3];
    const float* kv_m   = (const float*)d_in[4];
    const float* kv_v   = (const float*)d_in[5];
    const float* q_w    = (const float*)d_in[6];
    const float* q_g    = (const float*)d_in[7];
    const float* q_b    = (const float*)d_in[8];
    const float* q_m    = (const float*)d_in[9];
    const float* q_v    = (const float*)d_in[10];
    const float* proj_w = (const float*)d_in[11];
    const float* proj_g = (const float*)d_in[12];
    const float* proj_b = (const float*)d_in[13];
    const float* proj_m = (const float*)d_in[14];
    const float* proj_v = (const float*)d_in[15];
    const float* ab     = (const float*)d_in[16];
    const int*   idxs   = (const int*)  d_in[17];
    const int n_off = in_sizes[16] / 8;

    float* out = (float*)d_out;

    __half *p_kv, *p_q, *p_att;
    cudaGetSymbolAddress((void**)&p_kv,  g_kv);
    cudaGetSymbolAddress((void**)&p_q,   g_q);
    cudaGetSymbolAddress((void**)&p_att, g_att);

    // side stream + events (created once; host objects, no device allocations)
    static cudaStream_t s1 = nullptr;
    static cudaEvent_t evFork = nullptr, evJoin = nullptr;
    if (s1 == nullptr) {
        cudaStreamCreateWithFlags(&s1, cudaStreamNonBlocking);
        cudaEventCreateWithFlags(&evFork, cudaEventDisableTiming);
        cudaEventCreateWithFlags(&evJoin, cudaEventDisableTiming);
    }

    // ---- fork: gather + q GEMM on s1, kv GEMM on the main (capture) stream
    cudaEventRecord(evFork, 0);
    cudaStreamWaitEvent(s1, evFork, 0);

    bias_gather_kernel<<<dim3(196, 8), 392, 0, s1>>>(ab, idxs, n_off);
    conv_bn_hsw_tc_kernel<true, float, __half><<<dim3(1, 98), 256, 0, s1>>>(
        x, 256 * 784, 784, q_w, 256, q_g, q_b, q_m, q_v, p_q, 128, 196);
    cudaEventRecord(evJoin, s1);

    conv_bn_hsw_tc_kernel<false, float, __half><<<dim3(3, 392), 256>>>(
        x, 256 * 784, 784, kv_w, 256, kv_g, kv_b, kv_m, kv_v, p_kv, 384, 784);

    // ---- join, then attention + proj on the main stream
    cudaStreamWaitEvent(0, evJoin, 0);

    attention_tc_kernel<<<dim3(512, 2), 256>>>();

    conv_bn_hsw_tc_kernel<false, __half, float><<<dim3(4, 98), 256>>>(
        p_att, 256 * 196, 196, proj_w, 256, proj_g, proj_b, proj_m, proj_v, out, 512, 196);
}